// round 1
// baseline (speedup 1.0000x reference)
#include <cuda_runtime.h>

#define D 128
#define TILE 128
#define NSEG 50000
#define NTHREADS 256

// Scratch (no cudaMalloc allowed): segment sums, counts, stage buffers.
__device__ float g_segsum[NSEG * D];
__device__ float g_cnt[NSEG];
__device__ float g_u[NSEG * D];
__device__ float g_v[NSEG * D];

__global__ void zero_kernel() {
    int i = blockIdx.x * blockDim.x + threadIdx.x;
    if (i < NSEG * D) g_segsum[i] = 0.f;
    if (i < NSEG) g_cnt[i] = 0.f;
}

// ---------------------------------------------------------------------------
// K1: h1 = relu(x @ W1 + b1) for a 128-row tile, then segment-sum the tile
// (batch sorted => contiguous runs) with atomicAdd into g_segsum / g_cnt.
// smem: W1 (64KB) + x/h tile (64KB) + b1 + seg ids ~= 128.5KB -> 1 CTA/SM.
// 256 threads, each computes an 8x8 register tile -> FFMA-pipe bound.
// ---------------------------------------------------------------------------
__global__ __launch_bounds__(NTHREADS) void phi1_seg_kernel(
    const float* __restrict__ ins, const int* __restrict__ batch,
    const float* __restrict__ W1, const float* __restrict__ b1, int N)
{
    extern __shared__ float smem[];
    float* sW  = smem;                 // [D*D]
    float* sX  = smem + D * D;         // [TILE*D], reused for h1
    float* sB  = sX + TILE * D;        // [D]
    int*   sSeg = (int*)(sB + D);      // [TILE]

    const int tid = threadIdx.x;
    const long long row0 = (long long)blockIdx.x * TILE;

    for (int i = tid; i < D * D; i += NTHREADS) sW[i] = W1[i];
    if (tid < D) sB[tid] = b1[tid];
    for (int i = tid; i < TILE * D; i += NTHREADS) {
        int r = i >> 7, c = i & (D - 1);
        long long gr = row0 + r;
        sX[i] = (gr < N) ? ins[gr * D + c] : 0.f;
    }
    if (tid < TILE) {
        long long gr = row0 + tid;
        sSeg[tid] = (gr < N) ? batch[gr] : -1;
    }
    __syncthreads();

    const int tx = tid & 15, ty = tid >> 4;
    float acc[8][8];
#pragma unroll
    for (int i = 0; i < 8; i++)
#pragma unroll
        for (int j = 0; j < 8; j++) acc[i][j] = 0.f;

    const float* xb = sX + ty * 8 * D;
    const float* wb = sW + tx * 8;
#pragma unroll 2
    for (int k = 0; k < D; k++) {
        float a[8];
#pragma unroll
        for (int i = 0; i < 8; i++) a[i] = xb[i * D + k];
        float4 w0 = *(const float4*)(wb + k * D);
        float4 w1 = *(const float4*)(wb + k * D + 4);
#pragma unroll
        for (int i = 0; i < 8; i++) {
            acc[i][0] = fmaf(a[i], w0.x, acc[i][0]);
            acc[i][1] = fmaf(a[i], w0.y, acc[i][1]);
            acc[i][2] = fmaf(a[i], w0.z, acc[i][2]);
            acc[i][3] = fmaf(a[i], w0.w, acc[i][3]);
            acc[i][4] = fmaf(a[i], w1.x, acc[i][4]);
            acc[i][5] = fmaf(a[i], w1.y, acc[i][5]);
            acc[i][6] = fmaf(a[i], w1.z, acc[i][6]);
            acc[i][7] = fmaf(a[i], w1.w, acc[i][7]);
        }
    }
    __syncthreads();   // everyone done reading sX

    // bias + relu -> write h1 tile into sX
#pragma unroll
    for (int i = 0; i < 8; i++)
#pragma unroll
        for (int j = 0; j < 8; j++) {
            float v = acc[i][j] + sB[tx * 8 + j];
            sX[(ty * 8 + i) * D + tx * 8 + j] = fmaxf(v, 0.f);
        }
    __syncthreads();

    // Segment reduction: thread handles one column over half the tile rows.
    const int col = tid & (D - 1);
    const int rbeg = (tid >> 7) * (TILE / 2);
    int cur = sSeg[rbeg];
    float run = 0.f, cnt = 0.f;
    for (int r = rbeg; r < rbeg + TILE / 2; r++) {
        int s = sSeg[r];
        if (s != cur) {
            if (cur >= 0) {
                atomicAdd(&g_segsum[(size_t)cur * D + col], run);
                if (col == 0) atomicAdd(&g_cnt[cur], cnt);
            }
            cur = s; run = 0.f; cnt = 0.f;
        }
        run += sX[r * D + col];
        cnt += 1.f;
    }
    if (cur >= 0) {
        atomicAdd(&g_segsum[(size_t)cur * D + col], run);
        if (col == 0) atomicAdd(&g_cnt[cur], cnt);
    }
}

// ---------------------------------------------------------------------------
// Generic 128-wide row MLP layer: out = [relu](in' @ W + b)
//   MEAN_IN:   in' = in / max(cnt,1)   (in = g_segsum)
//   ZERO_EMPTY: rows with cnt==0 output 0 (matches reference seg_mean=0 -> rho)
// ---------------------------------------------------------------------------
template <bool MEAN_IN, bool RELU_OUT, bool ZERO_EMPTY>
__global__ __launch_bounds__(NTHREADS) void mlp_kernel(
    const float* __restrict__ in, const float* __restrict__ W,
    const float* __restrict__ bias, float* __restrict__ out, int nrows)
{
    extern __shared__ float smem[];
    float* sW   = smem;
    float* sX   = smem + D * D;
    float* sB   = sX + TILE * D;
    float* sCnt = sB + D;   // [TILE]

    const int tid = threadIdx.x;
    const int row0 = blockIdx.x * TILE;

    for (int i = tid; i < D * D; i += NTHREADS) sW[i] = W[i];
    if (tid < D) sB[tid] = bias[tid];
    if (tid < TILE) {
        int gr = row0 + tid;
        sCnt[tid] = (MEAN_IN || ZERO_EMPTY)
                        ? ((gr < nrows) ? g_cnt[gr] : 0.f) : 1.f;
    }
    __syncthreads();

    for (int i = tid; i < TILE * D; i += NTHREADS) {
        int r = i >> 7, c = i & (D - 1);
        int gr = row0 + r;
        float v = 0.f;
        if (gr < nrows) {
            v = in[(size_t)gr * D + c];
            if (MEAN_IN) v *= 1.f / fmaxf(sCnt[r], 1.f);
        }
        sX[i] = v;
    }
    __syncthreads();

    const int tx = tid & 15, ty = tid >> 4;
    float acc[8][8];
#pragma unroll
    for (int i = 0; i < 8; i++)
#pragma unroll
        for (int j = 0; j < 8; j++) acc[i][j] = 0.f;

    const float* xb = sX + ty * 8 * D;
    const float* wb = sW + tx * 8;
#pragma unroll 2
    for (int k = 0; k < D; k++) {
        float a[8];
#pragma unroll
        for (int i = 0; i < 8; i++) a[i] = xb[i * D + k];
        float4 w0 = *(const float4*)(wb + k * D);
        float4 w1 = *(const float4*)(wb + k * D + 4);
#pragma unroll
        for (int i = 0; i < 8; i++) {
            acc[i][0] = fmaf(a[i], w0.x, acc[i][0]);
            acc[i][1] = fmaf(a[i], w0.y, acc[i][1]);
            acc[i][2] = fmaf(a[i], w0.z, acc[i][2]);
            acc[i][3] = fmaf(a[i], w0.w, acc[i][3]);
            acc[i][4] = fmaf(a[i], w1.x, acc[i][4]);
            acc[i][5] = fmaf(a[i], w1.y, acc[i][5]);
            acc[i][6] = fmaf(a[i], w1.z, acc[i][6]);
            acc[i][7] = fmaf(a[i], w1.w, acc[i][7]);
        }
    }

#pragma unroll
    for (int i = 0; i < 8; i++) {
        int r = ty * 8 + i;
        int gr = row0 + r;
        if (gr < nrows) {
            bool empty = ZERO_EMPTY && (sCnt[r] <= 0.f);
#pragma unroll
            for (int j = 0; j < 8; j++) {
                float v = acc[i][j] + sB[tx * 8 + j];
                if (RELU_OUT) v = fmaxf(v, 0.f);
                if (empty) v = 0.f;
                out[(size_t)gr * D + tx * 8 + j] = v;
            }
        }
    }
}

extern "C" void kernel_launch(void* const* d_in, const int* in_sizes, int n_in,
                              void* d_out, int out_size)
{
    const float* ins    = (const float*)d_in[0];
    const int*   batch  = (const int*)d_in[1];   // jax x64 off => int32
    // d_in[2] = dim (always 0), ignored
    const float* phi_W1 = (const float*)d_in[3];
    const float* phi_b1 = (const float*)d_in[4];
    const float* phi_W2 = (const float*)d_in[5];
    const float* phi_b2 = (const float*)d_in[6];
    const float* rho_W1 = (const float*)d_in[7];
    const float* rho_b1 = (const float*)d_in[8];
    const float* rho_W2 = (const float*)d_in[9];
    const float* rho_b2 = (const float*)d_in[10];
    float* out = (float*)d_out;

    const int N = in_sizes[0] / D;
    const size_t SMEM = (size_t)(D * D + TILE * D + D + TILE) * sizeof(float);

    cudaFuncSetAttribute(phi1_seg_kernel,
                         cudaFuncAttributeMaxDynamicSharedMemorySize, (int)SMEM);
    cudaFuncSetAttribute(mlp_kernel<true,  false, true >,
                         cudaFuncAttributeMaxDynamicSharedMemorySize, (int)SMEM);
    cudaFuncSetAttribute(mlp_kernel<false, true,  false>,
                         cudaFuncAttributeMaxDynamicSharedMemorySize, (int)SMEM);
    cudaFuncSetAttribute(mlp_kernel<false, false, false>,
                         cudaFuncAttributeMaxDynamicSharedMemorySize, (int)SMEM);

    void *p_seg = nullptr, *p_u = nullptr, *p_v = nullptr;
    cudaGetSymbolAddress(&p_seg, g_segsum);
    cudaGetSymbolAddress(&p_u, g_u);
    cudaGetSymbolAddress(&p_v, g_v);

    int zgrid = (NSEG * D + NTHREADS - 1) / NTHREADS;
    zero_kernel<<<zgrid, NTHREADS>>>();

    int g1 = (N + TILE - 1) / TILE;
    phi1_seg_kernel<<<g1, NTHREADS, SMEM>>>(ins, batch, phi_W1, phi_b1, N);

    int g2 = (NSEG + TILE - 1) / TILE;
    // u = seg_mean(h1) @ W2 + b2   (0 for empty segments)
    mlp_kernel<true,  false, true ><<<g2, NTHREADS, SMEM>>>(
        (const float*)p_seg, phi_W2, phi_b2, (float*)p_u, NSEG);
    // v = relu(u @ rho_W1 + rho_b1)
    mlp_kernel<false, true,  false><<<g2, NTHREADS, SMEM>>>(
        (const float*)p_u, rho_W1, rho_b1, (float*)p_v, NSEG);
    // out = v @ rho_W2 + rho_b2
    mlp_kernel<false, false, false><<<g2, NTHREADS, SMEM>>>(
        (const float*)p_v, rho_W2, rho_b2, out, NSEG);
}

// round 3
// speedup vs baseline: 1.6349x; 1.6349x over previous
#include <cuda_runtime.h>
#include <cuda_bf16.h>
#include <cstdint>

#define D 128
#define TILE 128
#define NSEG 50000
#define NT 256

// ---------------- device scratch ----------------
__device__ __align__(16) float g_segsum[NSEG * D];
__device__ __align__(16) float g_cnt[NSEG];
__device__ __align__(16) float g_u[NSEG * D];
__device__ __align__(16) float g_v[NSEG * D];
// transposed weights Wt[n][k] = W[k][n], bf16 hi/lo split, 4 matrices
__device__ __align__(16) __nv_bfloat16 g_Whi[4][D * D];
__device__ __align__(16) __nv_bfloat16 g_Wlo[4][D * D];

// ---------------- smem layout (bytes) ----------------
// padded tile row: 128 bf16 + 8 pad = 136 halfwords = 272 B (conflict-free ldmatrix)
#define SROW 272u
#define SA_HI 0u
#define SA_LO 34816u
#define SW_HI 69632u
#define SW_LO 104448u
#define SBIAS 139264u     // 512 B
#define SMETA 139776u     // 512 B (seg ids int / counts float)
#define SH    0u          // epilogue h tile reuse, stride 512 B (128 f32)
#define SMEM_BYTES 140288u

__device__ __forceinline__ uint32_t smem_u32(const void* p) {
    return (uint32_t)__cvta_generic_to_shared(p);
}

#define LDSM_X4(r0, r1, r2, r3, addr)                                         \
    asm volatile("ldmatrix.sync.aligned.m8n8.x4.shared.b16 {%0,%1,%2,%3}, [%4];" \
                 : "=r"(r0), "=r"(r1), "=r"(r2), "=r"(r3) : "r"(addr))

#define MMA16816(d, a0, a1, a2, a3, b0, b1)                                   \
    asm volatile("mma.sync.aligned.m16n8k16.row.col.f32.bf16.bf16.f32 "       \
                 "{%0,%1,%2,%3},{%4,%5,%6,%7},{%8,%9},{%0,%1,%2,%3};"         \
                 : "+f"((d)[0]), "+f"((d)[1]), "+f"((d)[2]), "+f"((d)[3])     \
                 : "r"(a0), "r"(a1), "r"(a2), "r"(a3), "r"(b0), "r"(b1))

__device__ __forceinline__ uint32_t pack_bf2(float x, float y) {
    __nv_bfloat162 t = __floats2bfloat162_rn(x, y);
    return *(uint32_t*)&t;
}

// ---------------------------------------------------------------------------
// prep: transpose + bf16 hi/lo split all 4 weight matrices
// ---------------------------------------------------------------------------
__global__ void prep_kernel(const float* __restrict__ W0, const float* __restrict__ W1,
                            const float* __restrict__ W2, const float* __restrict__ W3) {
    int i = blockIdx.x * blockDim.x + threadIdx.x;
    if (i >= 4 * D * D) return;
    const float* Ws[4] = {W0, W1, W2, W3};
    int mat = i >> 14;
    int e = i & (D * D - 1);
    int n = e >> 7, k = e & (D - 1);
    float w = Ws[mat][k * D + n];
    __nv_bfloat16 hi = __float2bfloat16_rn(w);
    float lo = w - __bfloat162float(hi);
    g_Whi[mat][n * D + k] = hi;
    g_Wlo[mat][n * D + k] = __float2bfloat16_rn(lo);
}

__global__ void zero_kernel() {
    int i = blockIdx.x * blockDim.x + threadIdx.x;
    if (i < NSEG * D) g_segsum[i] = 0.f;
    if (i < NSEG) g_cnt[i] = 0.f;
}

// ---------------------------------------------------------------------------
// Unified mma.sync layer kernel. One CTA = 128-row tile, 8 warps x 16 rows.
//   MODE 0: h = relu(x@W+b); segment-sum into g_segsum/g_cnt (sorted batch)
//   MODE 1: out = mean(in)@W + b; empty segments -> 0
//   MODE 2: out = relu(in@W + b)
//   MODE 3: out = in@W + b
// 3xBF16 split: acc = Ahi*Whi + Alo*Whi + Ahi*Wlo (fp32 accum)
// ---------------------------------------------------------------------------
template <int MODE>
__global__ __launch_bounds__(NT, 1) void layer_kernel(
    const float* __restrict__ A_in, const int* __restrict__ batch,
    const __nv_bfloat16* __restrict__ Whi, const __nv_bfloat16* __restrict__ Wlo,
    const float* __restrict__ bias, float* __restrict__ outp, int nrows)
{
    extern __shared__ __align__(16) char smem[];
    const uint32_t sbase = smem_u32(smem);
    const int tid = threadIdx.x;
    const int wid = tid >> 5;
    const int lane = tid & 31;
    const int row0 = blockIdx.x * TILE;

    float* sB = (float*)(smem + SBIAS);
    float* sCnt = (float*)(smem + SMETA);
    int* sSeg = (int*)(smem + SMETA);

    if (tid < D) sB[tid] = bias[tid];
    if (MODE == 0) {
        if (tid < TILE) {
            int gr = row0 + tid;
            sSeg[tid] = (gr < nrows) ? batch[gr] : -1;
        }
    } else if (MODE == 1) {
        if (tid < TILE) {
            int gr = row0 + tid;
            sCnt[tid] = (gr < nrows) ? g_cnt[gr] : 0.f;
        }
    }
    if (MODE == 1) __syncthreads();   // sCnt needed by A-load scaling

    // ---- load A tile (fp32), split to bf16 hi/lo in padded smem ----
    for (int idx = tid; idx < TILE * 32; idx += NT) {
        int r = idx >> 5, c4 = idx & 31;          // c4: which float4 (4 cols)
        float4 v = make_float4(0.f, 0.f, 0.f, 0.f);
        int gr = row0 + r;
        if (gr < nrows) v = *(const float4*)(A_in + (size_t)gr * D + c4 * 4);
        if (MODE == 1) {
            float s = 1.f / fmaxf(sCnt[r], 1.f);
            v.x *= s; v.y *= s; v.z *= s; v.w *= s;
        }
        float hx = __bfloat162float(__float2bfloat16_rn(v.x));
        float hy = __bfloat162float(__float2bfloat16_rn(v.y));
        float hz = __bfloat162float(__float2bfloat16_rn(v.z));
        float hw = __bfloat162float(__float2bfloat16_rn(v.w));
        uint32_t off = (uint32_t)r * SROW + (uint32_t)c4 * 8;
        uint2 hi = make_uint2(pack_bf2(hx, hy), pack_bf2(hz, hw));
        uint2 lo = make_uint2(pack_bf2(v.x - hx, v.y - hy), pack_bf2(v.z - hz, v.w - hw));
        *(uint2*)(smem + SA_HI + off) = hi;
        *(uint2*)(smem + SA_LO + off) = lo;
    }
    // ---- load weights (bf16, pre-transposed/pre-split) into padded smem ----
    for (int idx = tid; idx < TILE * 16; idx += NT) {   // 16 x 16B chunks per row
        int r = idx >> 4, ch = idx & 15;
        uint32_t off = (uint32_t)r * SROW + (uint32_t)ch * 16;
        *(uint4*)(smem + SW_HI + off) = *(const uint4*)(Whi + r * D + ch * 8);
        *(uint4*)(smem + SW_LO + off) = *(const uint4*)(Wlo + r * D + ch * 8);
    }
    __syncthreads();

    // ---- mma mainloop ----
    float acc[16][4];
#pragma unroll
    for (int i = 0; i < 16; i++)
#pragma unroll
        for (int j = 0; j < 4; j++) acc[i][j] = 0.f;

    // A frag addresses: row = wid*16 + (lane&15), col halfword = (lane>>4)*8
    const uint32_t aRow = (uint32_t)(wid * 16 + (lane & 15));
    const uint32_t aColB = (uint32_t)((lane >> 4) * 16);
    uint32_t aHi = sbase + SA_HI + aRow * SROW + aColB;
    uint32_t aLo = sbase + SA_LO + aRow * SROW + aColB;
    // B frag addresses: n = (lane&7) + ((lane&16)?8:0), k halfword-base = (lane&8)?8:0
    const uint32_t bRow = (uint32_t)((lane & 7) + ((lane & 16) ? 8 : 0));
    const uint32_t bColB = (uint32_t)(((lane & 8) ? 8 : 0) * 2);
    const uint32_t bOff = bRow * SROW + bColB;

    for (int k = 0; k < 8; k++) {
        uint32_t ah0, ah1, ah2, ah3, al0, al1, al2, al3;
        LDSM_X4(ah0, ah1, ah2, ah3, aHi);
        LDSM_X4(al0, al1, al2, al3, aLo);
        uint32_t bh = sbase + SW_HI + bOff + (uint32_t)k * 32;
        uint32_t bl = sbase + SW_LO + bOff + (uint32_t)k * 32;
#pragma unroll
        for (int nt2 = 0; nt2 < 8; nt2++) {
            uint32_t w0, w1, w2, w3, v0, v1, v2, v3;
            LDSM_X4(w0, w1, w2, w3, bh);
            MMA16816(acc[2 * nt2],     ah0, ah1, ah2, ah3, w0, w1);
            MMA16816(acc[2 * nt2 + 1], ah0, ah1, ah2, ah3, w2, w3);
            MMA16816(acc[2 * nt2],     al0, al1, al2, al3, w0, w1);
            MMA16816(acc[2 * nt2 + 1], al0, al1, al2, al3, w2, w3);
            LDSM_X4(v0, v1, v2, v3, bl);
            MMA16816(acc[2 * nt2],     ah0, ah1, ah2, ah3, v0, v1);
            MMA16816(acc[2 * nt2 + 1], ah0, ah1, ah2, ah3, v2, v3);
            bh += 16 * SROW;
            bl += 16 * SROW;
        }
        aHi += 32;
        aLo += 32;
    }
    __syncthreads();   // done reading A/W smem (epilogue reuses region)

    // ---- epilogue ----
    const int grp = lane >> 2;          // 0..7 (row within 8)
    const int qp = lane & 3;            // col pair
    const int rA = wid * 16 + grp;      // tile-local rows rA, rA+8

    if (MODE == 0) {
        float* sH = (float*)(smem + SH);
#pragma unroll
        for (int nt = 0; nt < 16; nt++) {
            int c = nt * 8 + qp * 2;
            float b0 = sB[c], b1 = sB[c + 1];
            *(float2*)(sH + rA * 128 + c) =
                make_float2(fmaxf(acc[nt][0] + b0, 0.f), fmaxf(acc[nt][1] + b1, 0.f));
            *(float2*)(sH + (rA + 8) * 128 + c) =
                make_float2(fmaxf(acc[nt][2] + b0, 0.f), fmaxf(acc[nt][3] + b1, 0.f));
        }
        __syncthreads();
        // segment reduce: thread = (half, col); sorted batch -> contiguous runs
        const int col = tid & (D - 1);
        const int rbeg = (tid >> 7) * (TILE / 2);
        int cur = sSeg[rbeg];
        float run = 0.f, cnt = 0.f;
        for (int r = rbeg; r < rbeg + TILE / 2; r++) {
            int s = sSeg[r];
            if (s != cur) {
                if (cur >= 0) {
                    atomicAdd(&g_segsum[(size_t)cur * D + col], run);
                    if (col == 0) atomicAdd(&g_cnt[cur], cnt);
                }
                cur = s; run = 0.f; cnt = 0.f;
            }
            run += sH[r * 128 + col];
            cnt += 1.f;
        }
        if (cur >= 0) {
            atomicAdd(&g_segsum[(size_t)cur * D + col], run);
            if (col == 0) atomicAdd(&g_cnt[cur], cnt);
        }
    } else {
        int gr0 = row0 + rA, gr1 = row0 + rA + 8;
        bool z0 = (MODE == 1) && (sCnt[rA] <= 0.f);
        bool z1 = (MODE == 1) && (sCnt[rA + 8] <= 0.f);
#pragma unroll
        for (int nt = 0; nt < 16; nt++) {
            int c = nt * 8 + qp * 2;
            float b0 = sB[c], b1 = sB[c + 1];
            if (gr0 < nrows) {
                float x = acc[nt][0] + b0, y = acc[nt][1] + b1;
                if (MODE == 2) { x = fmaxf(x, 0.f); y = fmaxf(y, 0.f); }
                if (z0) { x = 0.f; y = 0.f; }
                *(float2*)(outp + (size_t)gr0 * D + c) = make_float2(x, y);
            }
            if (gr1 < nrows) {
                float x = acc[nt][2] + b0, y = acc[nt][3] + b1;
                if (MODE == 2) { x = fmaxf(x, 0.f); y = fmaxf(y, 0.f); }
                if (z1) { x = 0.f; y = 0.f; }
                *(float2*)(outp + (size_t)gr1 * D + c) = make_float2(x, y);
            }
        }
    }
}

// ---------------------------------------------------------------------------
extern "C" void kernel_launch(void* const* d_in, const int* in_sizes, int n_in,
                              void* d_out, int out_size)
{
    const float* ins    = (const float*)d_in[0];
    const int*   batch  = (const int*)d_in[1];
    const float* phi_W1 = (const float*)d_in[3];
    const float* phi_b1 = (const float*)d_in[4];
    const float* phi_W2 = (const float*)d_in[5];
    const float* phi_b2 = (const float*)d_in[6];
    const float* rho_W1 = (const float*)d_in[7];
    const float* rho_b1 = (const float*)d_in[8];
    const float* rho_W2 = (const float*)d_in[9];
    const float* rho_b2 = (const float*)d_in[10];
    float* out = (float*)d_out;

    const int N = in_sizes[0] / D;

    cudaFuncSetAttribute(layer_kernel<0>, cudaFuncAttributeMaxDynamicSharedMemorySize, SMEM_BYTES);
    cudaFuncSetAttribute(layer_kernel<1>, cudaFuncAttributeMaxDynamicSharedMemorySize, SMEM_BYTES);
    cudaFuncSetAttribute(layer_kernel<2>, cudaFuncAttributeMaxDynamicSharedMemorySize, SMEM_BYTES);
    cudaFuncSetAttribute(layer_kernel<3>, cudaFuncAttributeMaxDynamicSharedMemorySize, SMEM_BYTES);

    void *p_seg = nullptr, *p_u = nullptr, *p_v = nullptr;
    void *p_whi = nullptr, *p_wlo = nullptr;
    cudaGetSymbolAddress(&p_seg, g_segsum);
    cudaGetSymbolAddress(&p_u, g_u);
    cudaGetSymbolAddress(&p_v, g_v);
    cudaGetSymbolAddress(&p_whi, g_Whi);
    cudaGetSymbolAddress(&p_wlo, g_Wlo);
    const __nv_bfloat16* Whi = (const __nv_bfloat16*)p_whi;
    const __nv_bfloat16* Wlo = (const __nv_bfloat16*)p_wlo;

    int zgrid = (NSEG * D + NT - 1) / NT;
    zero_kernel<<<zgrid, NT>>>();
    prep_kernel<<<(4 * D * D + NT - 1) / NT, NT>>>(phi_W1, phi_W2, rho_W1, rho_W2);

    int g1 = (N + TILE - 1) / TILE;
    layer_kernel<0><<<g1, NT, SMEM_BYTES>>>(ins, batch,
        Whi + 0 * D * D, Wlo + 0 * D * D, phi_b1, nullptr, N);

    int g2 = (NSEG + TILE - 1) / TILE;
    layer_kernel<1><<<g2, NT, SMEM_BYTES>>>((const float*)p_seg, nullptr,
        Whi + 1 * D * D, Wlo + 1 * D * D, phi_b2, (float*)p_u, NSEG);
    layer_kernel<2><<<g2, NT, SMEM_BYTES>>>((const float*)p_u, nullptr,
        Whi + 2 * D * D, Wlo + 2 * D * D, rho_b1, (float*)p_v, NSEG);
    layer_kernel<3><<<g2, NT, SMEM_BYTES>>>((const float*)p_v, nullptr,
        Whi + 3 * D * D, Wlo + 3 * D * D, rho_b2, out, NSEG);
}

// round 4
// speedup vs baseline: 2.4275x; 1.4848x over previous
#include <cuda_runtime.h>
#include <cuda_bf16.h>
#include <cstdint>

#define D 128
#define TILE 128
#define NSEG 50000
#define NT 256

// ---------------- device scratch ----------------
__device__ __align__(16) float g_segsum[NSEG * D];
__device__ __align__(16) float g_cnt[NSEG];
// transposed weights Wt[n][k] = W[k][n], bf16 hi/lo split, 4 matrices
__device__ __align__(16) __nv_bfloat16 g_Whi[4][D * D];
__device__ __align__(16) __nv_bfloat16 g_Wlo[4][D * D];

// ---------------- smem layout (bytes), 104 KB/CTA -> 2 CTAs/SM ----------------
// padded tile row: 128 bf16 + 8 pad = 272 B (conflict-free ldmatrix)
#define SROW 272u
#define SA_HI 0u
#define SA_LO 34816u
#define SW    69632u
#define SBIAS 104448u   // 3 x 512 B
#define SMETA 105984u   // 512 B (seg ids int / counts float)
#define SMEM_BYTES 106496u

__device__ __forceinline__ uint32_t smem_u32(const void* p) {
    return (uint32_t)__cvta_generic_to_shared(p);
}

#define LDSM_X4(r0, r1, r2, r3, addr)                                         \
    asm volatile("ldmatrix.sync.aligned.m8n8.x4.shared.b16 {%0,%1,%2,%3}, [%4];" \
                 : "=r"(r0), "=r"(r1), "=r"(r2), "=r"(r3) : "r"(addr))

#define MMA16816(d, a0, a1, a2, a3, b0, b1)                                   \
    asm volatile("mma.sync.aligned.m16n8k16.row.col.f32.bf16.bf16.f32 "       \
                 "{%0,%1,%2,%3},{%4,%5,%6,%7},{%8,%9},{%0,%1,%2,%3};"         \
                 : "+f"((d)[0]), "+f"((d)[1]), "+f"((d)[2]), "+f"((d)[3])     \
                 : "r"(a0), "r"(a1), "r"(a2), "r"(a3), "r"(b0), "r"(b1))

__device__ __forceinline__ uint32_t pack_bf2(float x, float y) {
    __nv_bfloat162 t = __floats2bfloat162_rn(x, y);
    return *(uint32_t*)&t;
}

// ---------------------------------------------------------------------------
__global__ void prep_kernel(const float* __restrict__ W0, const float* __restrict__ W1,
                            const float* __restrict__ W2, const float* __restrict__ W3) {
    int i = blockIdx.x * blockDim.x + threadIdx.x;
    if (i >= 4 * D * D) return;
    const float* Ws[4] = {W0, W1, W2, W3};
    int mat = i >> 14;
    int e = i & (D * D - 1);
    int n = e >> 7, k = e & (D - 1);
    float w = Ws[mat][k * D + n];
    __nv_bfloat16 hi = __float2bfloat16_rn(w);
    float lo = w - __bfloat162float(hi);
    g_Whi[mat][n * D + k] = hi;
    g_Wlo[mat][n * D + k] = __float2bfloat16_rn(lo);
}

__global__ void zero_kernel() {
    int i = blockIdx.x * blockDim.x + threadIdx.x;
    if (i < NSEG * D) g_segsum[i] = 0.f;
    if (i < NSEG) g_cnt[i] = 0.f;
}

// ---------------------------------------------------------------------------
// shared building blocks
// ---------------------------------------------------------------------------
__device__ __forceinline__ void load_W(char* smem, const __nv_bfloat16* __restrict__ W,
                                       int tid) {
    for (int idx = tid; idx < TILE * 16; idx += NT) {
        int r = idx >> 4, ch = idx & 15;
        *(uint4*)(smem + SW + (uint32_t)r * SROW + (uint32_t)ch * 16) =
            *(const uint4*)(W + r * D + ch * 8);
    }
}

// one MMA pass over the whole tile with current W buffer.
// WITH_LO: also accumulate Alo x W.
template <bool WITH_LO>
__device__ __forceinline__ void gemm_pass(uint32_t sbase, float (*acc)[4],
                                          int wid, int lane) {
    const uint32_t aRow = (uint32_t)(wid * 16 + (lane & 15));
    const uint32_t aColB = (uint32_t)((lane >> 4) * 16);
    uint32_t aHi = sbase + SA_HI + aRow * SROW + aColB;
    uint32_t aLo = sbase + SA_LO + aRow * SROW + aColB;
    const uint32_t bRow = (uint32_t)((lane & 7) + ((lane & 16) ? 8 : 0));
    const uint32_t bColB = (uint32_t)(((lane & 8) ? 8 : 0) * 2);
    const uint32_t bBase = sbase + SW + bRow * SROW + bColB;

#pragma unroll 1
    for (int k = 0; k < 8; k++) {
        uint32_t ah0, ah1, ah2, ah3, al0, al1, al2, al3;
        LDSM_X4(ah0, ah1, ah2, ah3, aHi);
        if (WITH_LO) LDSM_X4(al0, al1, al2, al3, aLo);
        uint32_t bh = bBase + (uint32_t)k * 32;
        uint32_t w0, w1, w2, w3;
        LDSM_X4(w0, w1, w2, w3, bh);
#pragma unroll
        for (int nt2 = 0; nt2 < 8; nt2++) {
            uint32_t n0, n1, n2, n3;
            if (nt2 < 7) { LDSM_X4(n0, n1, n2, n3, bh + 16u * SROW); }
            MMA16816(acc[2 * nt2],     ah0, ah1, ah2, ah3, w0, w1);
            MMA16816(acc[2 * nt2 + 1], ah0, ah1, ah2, ah3, w2, w3);
            if (WITH_LO) {
                MMA16816(acc[2 * nt2],     al0, al1, al2, al3, w0, w1);
                MMA16816(acc[2 * nt2 + 1], al0, al1, al2, al3, w2, w3);
            }
            if (nt2 < 7) { w0 = n0; w1 = n1; w2 = n2; w3 = n3; }
            bh += 16u * SROW;
        }
        aHi += 32;
        aLo += 32;
    }
}

// full 3-term GEMM: acc += Ahi*Whi + Alo*Whi + Ahi*Wlo, single W buffer reloaded.
__device__ __forceinline__ void gemm3(char* smem, uint32_t sbase,
                                      const __nv_bfloat16* __restrict__ Whi,
                                      const __nv_bfloat16* __restrict__ Wlo,
                                      float (*acc)[4], int tid, int wid, int lane) {
    load_W(smem, Whi, tid);
    __syncthreads();
    gemm_pass<true>(sbase, acc, wid, lane);
    __syncthreads();
    load_W(smem, Wlo, tid);
    __syncthreads();
    gemm_pass<false>(sbase, acc, wid, lane);
    __syncthreads();
}

// write fragments (+bias, opt relu, opt zero-empty) back to A smem as bf16 hi/lo
__device__ __forceinline__ void frag_store_A(char* smem, float (*acc)[4],
                                             const float* bias, const float* sCnt,
                                             bool relu, bool zeroE, int wid, int lane) {
    const int grp = lane >> 2, qp = lane & 3;
    const int rA = wid * 16 + grp;
    bool z0 = zeroE && (sCnt[rA] <= 0.f);
    bool z1 = zeroE && (sCnt[rA + 8] <= 0.f);
#pragma unroll
    for (int nt = 0; nt < 16; nt++) {
        int c = nt * 8 + qp * 2;
        float b0 = bias[c], b1 = bias[c + 1];
        float x0 = acc[nt][0] + b0, y0 = acc[nt][1] + b1;
        float x1 = acc[nt][2] + b0, y1 = acc[nt][3] + b1;
        if (relu) {
            x0 = fmaxf(x0, 0.f); y0 = fmaxf(y0, 0.f);
            x1 = fmaxf(x1, 0.f); y1 = fmaxf(y1, 0.f);
        }
        if (z0) { x0 = 0.f; y0 = 0.f; }
        if (z1) { x1 = 0.f; y1 = 0.f; }
        float hx0 = __bfloat162float(__float2bfloat16_rn(x0));
        float hy0 = __bfloat162float(__float2bfloat16_rn(y0));
        float hx1 = __bfloat162float(__float2bfloat16_rn(x1));
        float hy1 = __bfloat162float(__float2bfloat16_rn(y1));
        uint32_t o0 = (uint32_t)rA * SROW + (uint32_t)c * 2;
        uint32_t o1 = (uint32_t)(rA + 8) * SROW + (uint32_t)c * 2;
        *(uint32_t*)(smem + SA_HI + o0) = pack_bf2(hx0, hy0);
        *(uint32_t*)(smem + SA_LO + o0) = pack_bf2(x0 - hx0, y0 - hy0);
        *(uint32_t*)(smem + SA_HI + o1) = pack_bf2(hx1, hy1);
        *(uint32_t*)(smem + SA_LO + o1) = pack_bf2(x1 - hx1, y1 - hy1);
    }
}

// ---------------------------------------------------------------------------
// phi layer 1 + segment reduce: h = relu(x@W1+b1); atomics into segsum/cnt
// ---------------------------------------------------------------------------
__global__ __launch_bounds__(NT, 2) void phi_seg_kernel(
    const float* __restrict__ ins, const int* __restrict__ batch,
    const __nv_bfloat16* __restrict__ Whi, const __nv_bfloat16* __restrict__ Wlo,
    const float* __restrict__ bias, int nrows)
{
    extern __shared__ __align__(16) char smem[];
    const uint32_t sbase = smem_u32(smem);
    const int tid = threadIdx.x, wid = tid >> 5, lane = tid & 31;
    const int row0 = blockIdx.x * TILE;

    float* sB = (float*)(smem + SBIAS);
    int* sSeg = (int*)(smem + SMETA);
    if (tid < D) sB[tid] = bias[tid];
    if (tid < TILE) {
        int gr = row0 + tid;
        sSeg[tid] = (gr < nrows) ? batch[gr] : -1;
    }
    // A tile: fp32 -> bf16 hi/lo
    for (int idx = tid; idx < TILE * 32; idx += NT) {
        int r = idx >> 5, c4 = idx & 31;
        float4 v = make_float4(0.f, 0.f, 0.f, 0.f);
        int gr = row0 + r;
        if (gr < nrows) v = *(const float4*)(ins + (size_t)gr * D + c4 * 4);
        float hx = __bfloat162float(__float2bfloat16_rn(v.x));
        float hy = __bfloat162float(__float2bfloat16_rn(v.y));
        float hz = __bfloat162float(__float2bfloat16_rn(v.z));
        float hw = __bfloat162float(__float2bfloat16_rn(v.w));
        uint32_t off = (uint32_t)r * SROW + (uint32_t)c4 * 8;
        *(uint2*)(smem + SA_HI + off) = make_uint2(pack_bf2(hx, hy), pack_bf2(hz, hw));
        *(uint2*)(smem + SA_LO + off) =
            make_uint2(pack_bf2(v.x - hx, v.y - hy), pack_bf2(v.z - hz, v.w - hw));
    }

    float acc[16][4];
#pragma unroll
    for (int i = 0; i < 16; i++)
#pragma unroll
        for (int j = 0; j < 4; j++) acc[i][j] = 0.f;

    gemm3(smem, sbase, Whi, Wlo, acc, tid, wid, lane);

    // epilogue: bias+relu -> sH (reuse A region), then segment reduce
    float* sH = (float*)smem;
    {
        const int grp = lane >> 2, qp = lane & 3;
        const int rA = wid * 16 + grp;
#pragma unroll
        for (int nt = 0; nt < 16; nt++) {
            int c = nt * 8 + qp * 2;
            float b0 = sB[c], b1 = sB[c + 1];
            *(float2*)(sH + rA * 128 + c) =
                make_float2(fmaxf(acc[nt][0] + b0, 0.f), fmaxf(acc[nt][1] + b1, 0.f));
            *(float2*)(sH + (rA + 8) * 128 + c) =
                make_float2(fmaxf(acc[nt][2] + b0, 0.f), fmaxf(acc[nt][3] + b1, 0.f));
        }
    }
    __syncthreads();
    const int col = tid & (D - 1);
    const int rbeg = (tid >> 7) * (TILE / 2);
    int cur = sSeg[rbeg];
    float run = 0.f, cnt = 0.f;
    for (int r = rbeg; r < rbeg + TILE / 2; r++) {
        int s = sSeg[r];
        if (s != cur) {
            if (cur >= 0) {
                atomicAdd(&g_segsum[(size_t)cur * D + col], run);
                if (col == 0) atomicAdd(&g_cnt[cur], cnt);
            }
            cur = s; run = 0.f; cnt = 0.f;
        }
        run += sH[r * 128 + col];
        cnt += 1.f;
    }
    if (cur >= 0) {
        atomicAdd(&g_segsum[(size_t)cur * D + col], run);
        if (col == 0) atomicAdd(&g_cnt[cur], cnt);
    }
}

// ---------------------------------------------------------------------------
// fused small path: u = mean@phiW2+b2 (zero-empty); v = relu(u@rhoW1+rb1);
// out = v@rhoW2+rb2. Tile stays in smem across all three GEMMs.
// ---------------------------------------------------------------------------
__global__ __launch_bounds__(NT, 2) void rho_fused_kernel(
    const __nv_bfloat16* __restrict__ W2hi, const __nv_bfloat16* __restrict__ W2lo,
    const __nv_bfloat16* __restrict__ R1hi, const __nv_bfloat16* __restrict__ R1lo,
    const __nv_bfloat16* __restrict__ R2hi, const __nv_bfloat16* __restrict__ R2lo,
    const float* __restrict__ b2, const float* __restrict__ rb1,
    const float* __restrict__ rb2, float* __restrict__ outp, int nrows)
{
    extern __shared__ __align__(16) char smem[];
    const uint32_t sbase = smem_u32(smem);
    const int tid = threadIdx.x, wid = tid >> 5, lane = tid & 31;
    const int row0 = blockIdx.x * TILE;

    float* sB = (float*)(smem + SBIAS);
    float* sCnt = (float*)(smem + SMETA);
    if (tid < D) {
        sB[tid] = b2[tid];
        sB[128 + tid] = rb1[tid];
        sB[256 + tid] = rb2[tid];
    }
    if (tid < TILE) {
        int gr = row0 + tid;
        sCnt[tid] = (gr < nrows) ? g_cnt[gr] : 0.f;
    }
    __syncthreads();

    // A tile: mean = segsum / max(cnt,1), split hi/lo
    for (int idx = tid; idx < TILE * 32; idx += NT) {
        int r = idx >> 5, c4 = idx & 31;
        float4 v = make_float4(0.f, 0.f, 0.f, 0.f);
        int gr = row0 + r;
        if (gr < nrows) {
            v = *(const float4*)(g_segsum + (size_t)gr * D + c4 * 4);
            float s = 1.f / fmaxf(sCnt[r], 1.f);
            v.x *= s; v.y *= s; v.z *= s; v.w *= s;
        }
        float hx = __bfloat162float(__float2bfloat16_rn(v.x));
        float hy = __bfloat162float(__float2bfloat16_rn(v.y));
        float hz = __bfloat162float(__float2bfloat16_rn(v.z));
        float hw = __bfloat162float(__float2bfloat16_rn(v.w));
        uint32_t off = (uint32_t)r * SROW + (uint32_t)c4 * 8;
        *(uint2*)(smem + SA_HI + off) = make_uint2(pack_bf2(hx, hy), pack_bf2(hz, hw));
        *(uint2*)(smem + SA_LO + off) =
            make_uint2(pack_bf2(v.x - hx, v.y - hy), pack_bf2(v.z - hz, v.w - hw));
    }

    float acc[16][4];
#pragma unroll
    for (int i = 0; i < 16; i++)
#pragma unroll
        for (int j = 0; j < 4; j++) acc[i][j] = 0.f;

    // GEMM 1: u = mean@phiW2 + b2, zero empty rows
    gemm3(smem, sbase, W2hi, W2lo, acc, tid, wid, lane);
    frag_store_A(smem, acc, sB, sCnt, false, true, wid, lane);
#pragma unroll
    for (int i = 0; i < 16; i++)
#pragma unroll
        for (int j = 0; j < 4; j++) acc[i][j] = 0.f;

    // GEMM 2: v = relu(u@rhoW1 + rb1)
    gemm3(smem, sbase, R1hi, R1lo, acc, tid, wid, lane);
    frag_store_A(smem, acc, sB + 128, sCnt, true, false, wid, lane);
#pragma unroll
    for (int i = 0; i < 16; i++)
#pragma unroll
        for (int j = 0; j < 4; j++) acc[i][j] = 0.f;

    // GEMM 3: out = v@rhoW2 + rb2
    gemm3(smem, sbase, R2hi, R2lo, acc, tid, wid, lane);
    {
        const int grp = lane >> 2, qp = lane & 3;
        const int rA = wid * 16 + grp;
        int gr0 = row0 + rA, gr1 = row0 + rA + 8;
#pragma unroll
        for (int nt = 0; nt < 16; nt++) {
            int c = nt * 8 + qp * 2;
            float b0 = sB[256 + c], b1 = sB[256 + c + 1];
            if (gr0 < nrows)
                *(float2*)(outp + (size_t)gr0 * D + c) =
                    make_float2(acc[nt][0] + b0, acc[nt][1] + b1);
            if (gr1 < nrows)
                *(float2*)(outp + (size_t)gr1 * D + c) =
                    make_float2(acc[nt][2] + b0, acc[nt][3] + b1);
        }
    }
}

// ---------------------------------------------------------------------------
extern "C" void kernel_launch(void* const* d_in, const int* in_sizes, int n_in,
                              void* d_out, int out_size)
{
    const float* ins    = (const float*)d_in[0];
    const int*   batch  = (const int*)d_in[1];
    const float* phi_W1 = (const float*)d_in[3];
    const float* phi_b1 = (const float*)d_in[4];
    const float* phi_W2 = (const float*)d_in[5];
    const float* phi_b2 = (const float*)d_in[6];
    const float* rho_W1 = (const float*)d_in[7];
    const float* rho_b1 = (const float*)d_in[8];
    const float* rho_W2 = (const float*)d_in[9];
    const float* rho_b2 = (const float*)d_in[10];
    float* out = (float*)d_out;

    const int N = in_sizes[0] / D;

    cudaFuncSetAttribute(phi_seg_kernel, cudaFuncAttributeMaxDynamicSharedMemorySize, SMEM_BYTES);
    cudaFuncSetAttribute(rho_fused_kernel, cudaFuncAttributeMaxDynamicSharedMemorySize, SMEM_BYTES);

    void *p_whi = nullptr, *p_wlo = nullptr;
    cudaGetSymbolAddress(&p_whi, g_Whi);
    cudaGetSymbolAddress(&p_wlo, g_Wlo);
    const __nv_bfloat16* Whi = (const __nv_bfloat16*)p_whi;
    const __nv_bfloat16* Wlo = (const __nv_bfloat16*)p_wlo;

    int zgrid = (NSEG * D + NT - 1) / NT;
    zero_kernel<<<zgrid, NT>>>();
    prep_kernel<<<(4 * D * D + NT - 1) / NT, NT>>>(phi_W1, phi_W2, rho_W1, rho_W2);

    int g1 = (N + TILE - 1) / TILE;
    phi_seg_kernel<<<g1, NT, SMEM_BYTES>>>(ins, batch,
        Whi + 0 * D * D, Wlo + 0 * D * D, phi_b1, N);

    int g2 = (NSEG + TILE - 1) / TILE;
    rho_fused_kernel<<<g2, NT, SMEM_BYTES>>>(
        Whi + 1 * D * D, Wlo + 1 * D * D,
        Whi + 2 * D * D, Wlo + 2 * D * D,
        Whi + 3 * D * D, Wlo + 3 * D * D,
        phi_b2, rho_b1, rho_b2, out, NSEG);
}

// round 5
// speedup vs baseline: 2.7179x; 1.1196x over previous
#include <cuda_runtime.h>
#include <cuda_bf16.h>
#include <cstdint>

#define D 128
#define TILE 128
#define NSEG 50000
#define NT 256

// ---------------- device scratch ----------------
__device__ __align__(16) float g_segsum[NSEG * D];
__device__ __align__(16) float g_cnt[NSEG];
// transposed weights Wt[n][k] = W[k][n], bf16 hi/lo split, 4 matrices
__device__ __align__(16) __nv_bfloat16 g_Whi[4][D * D];
__device__ __align__(16) __nv_bfloat16 g_Wlo[4][D * D];

// ---------------- smem layout (bytes) ----------------
// padded tile row: 128 bf16 + 8 pad = 272 B (conflict-free ldmatrix)
#define SROW 272u
#define SW_HI 0u
#define SW_LO 34816u
#define SA_HI 69632u
#define SA_LO 104448u
// phi persistent extras
#define STAGE 139264u      // fp32 A staging, 65536 B
#define PBIAS 204800u      // 512 B
#define PSEG0 205312u      // 512 B
#define PSEG1 205824u      // 512 B
#define PHI_SMEM 206336u
// rho extras
#define RBIAS 139264u      // 3 x 512 B
#define RCNT  140800u      // 512 B
#define RHO_SMEM 141312u

__device__ __forceinline__ uint32_t smem_u32(const void* p) {
    return (uint32_t)__cvta_generic_to_shared(p);
}

#define LDSM_X4(r0, r1, r2, r3, addr)                                         \
    asm volatile("ldmatrix.sync.aligned.m8n8.x4.shared.b16 {%0,%1,%2,%3}, [%4];" \
                 : "=r"(r0), "=r"(r1), "=r"(r2), "=r"(r3) : "r"(addr))

#define MMA16816(d, a0, a1, a2, a3, b0, b1)                                   \
    asm volatile("mma.sync.aligned.m16n8k16.row.col.f32.bf16.bf16.f32 "       \
                 "{%0,%1,%2,%3},{%4,%5,%6,%7},{%8,%9},{%0,%1,%2,%3};"         \
                 : "+f"((d)[0]), "+f"((d)[1]), "+f"((d)[2]), "+f"((d)[3])     \
                 : "r"(a0), "r"(a1), "r"(a2), "r"(a3), "r"(b0), "r"(b1))

__device__ __forceinline__ uint32_t pack_bf2(float x, float y) {
    __nv_bfloat162 t = __floats2bfloat162_rn(x, y);
    return *(uint32_t*)&t;
}
__device__ __forceinline__ void cp16(uint32_t dst, const void* src, int bytes) {
    asm volatile("cp.async.cg.shared.global [%0], [%1], 16, %2;"
                 :: "r"(dst), "l"(src), "r"(bytes) : "memory");
}
__device__ __forceinline__ void cp_commit() {
    asm volatile("cp.async.commit_group;" ::: "memory");
}
__device__ __forceinline__ void cp_wait0() {
    asm volatile("cp.async.wait_group 0;" ::: "memory");
}

// ---------------------------------------------------------------------------
__global__ void prep_kernel(const float* __restrict__ W0, const float* __restrict__ W1,
                            const float* __restrict__ W2, const float* __restrict__ W3) {
    int i = blockIdx.x * blockDim.x + threadIdx.x;
    if (i >= 4 * D * D) return;
    const float* Ws[4] = {W0, W1, W2, W3};
    int mat = i >> 14;
    int e = i & (D * D - 1);
    int n = e >> 7, k = e & (D - 1);
    float w = Ws[mat][k * D + n];
    __nv_bfloat16 hi = __float2bfloat16_rn(w);
    float lo = w - __bfloat162float(hi);
    g_Whi[mat][n * D + k] = hi;
    g_Wlo[mat][n * D + k] = __float2bfloat16_rn(lo);
}

__global__ void zero_kernel() {
    int i = blockIdx.x * blockDim.x + threadIdx.x;
    if (i < NSEG * D) g_segsum[i] = 0.f;
    if (i < NSEG) g_cnt[i] = 0.f;
}

// ---------------------------------------------------------------------------
__device__ __forceinline__ void load_W_pair(char* smem,
                                            const __nv_bfloat16* __restrict__ Whi,
                                            const __nv_bfloat16* __restrict__ Wlo,
                                            int tid) {
    for (int idx = tid; idx < TILE * 16; idx += NT) {
        int r = idx >> 4, ch = idx & 15;
        uint32_t off = (uint32_t)r * SROW + (uint32_t)ch * 16;
        *(uint4*)(smem + SW_HI + off) = *(const uint4*)(Whi + r * D + ch * 8);
        *(uint4*)(smem + SW_LO + off) = *(const uint4*)(Wlo + r * D + ch * 8);
    }
}

// combined 3-term pass: acc += Ahi*Whi + Alo*Whi + Ahi*Wlo (all smem-resident)
__device__ __forceinline__ void gemm_pass3(uint32_t sbase, float (*acc)[4],
                                           int wid, int lane) {
    const uint32_t aRow = (uint32_t)(wid * 16 + (lane & 15));
    const uint32_t aColB = (uint32_t)((lane >> 4) * 16);
    uint32_t aHi = sbase + SA_HI + aRow * SROW + aColB;
    uint32_t aLo = sbase + SA_LO + aRow * SROW + aColB;
    const uint32_t bRow = (uint32_t)((lane & 7) + ((lane & 16) ? 8 : 0));
    const uint32_t bColB = (uint32_t)(((lane & 8) ? 8 : 0) * 2);
    const uint32_t bHi0 = sbase + SW_HI + bRow * SROW + bColB;
    const uint32_t bLo0 = sbase + SW_LO + bRow * SROW + bColB;

#pragma unroll 1
    for (int k = 0; k < 8; k++) {
        uint32_t ah0, ah1, ah2, ah3, al0, al1, al2, al3;
        LDSM_X4(ah0, ah1, ah2, ah3, aHi);
        LDSM_X4(al0, al1, al2, al3, aLo);
        uint32_t bh = bHi0 + (uint32_t)k * 32;
        uint32_t bl = bLo0 + (uint32_t)k * 32;
        uint32_t w0, w1, w2, w3;
        LDSM_X4(w0, w1, w2, w3, bh);
#pragma unroll
        for (int nt2 = 0; nt2 < 8; nt2++) {
            uint32_t v0, v1, v2, v3, n0, n1, n2, n3;
            LDSM_X4(v0, v1, v2, v3, bl);
            if (nt2 < 7) { LDSM_X4(n0, n1, n2, n3, bh + 16u * SROW); }
            MMA16816(acc[2 * nt2],     ah0, ah1, ah2, ah3, w0, w1);
            MMA16816(acc[2 * nt2 + 1], ah0, ah1, ah2, ah3, w2, w3);
            MMA16816(acc[2 * nt2],     al0, al1, al2, al3, w0, w1);
            MMA16816(acc[2 * nt2 + 1], al0, al1, al2, al3, w2, w3);
            MMA16816(acc[2 * nt2],     ah0, ah1, ah2, ah3, v0, v1);
            MMA16816(acc[2 * nt2 + 1], ah0, ah1, ah2, ah3, v2, v3);
            if (nt2 < 7) { w0 = n0; w1 = n1; w2 = n2; w3 = n3; }
            bh += 16u * SROW;
            bl += 16u * SROW;
        }
        aHi += 32;
        aLo += 32;
    }
}

// fragments (+bias, opt relu, opt zero-empty) back to A smem as bf16 hi/lo
__device__ __forceinline__ void frag_store_A(char* smem, float (*acc)[4],
                                             const float* bias, const float* sCnt,
                                             bool relu, bool zeroE, int wid, int lane) {
    const int grp = lane >> 2, qp = lane & 3;
    const int rA = wid * 16 + grp;
    bool z0 = zeroE && (sCnt[rA] <= 0.f);
    bool z1 = zeroE && (sCnt[rA + 8] <= 0.f);
#pragma unroll
    for (int nt = 0; nt < 16; nt++) {
        int c = nt * 8 + qp * 2;
        float b0 = bias[c], b1 = bias[c + 1];
        float x0 = acc[nt][0] + b0, y0 = acc[nt][1] + b1;
        float x1 = acc[nt][2] + b0, y1 = acc[nt][3] + b1;
        if (relu) {
            x0 = fmaxf(x0, 0.f); y0 = fmaxf(y0, 0.f);
            x1 = fmaxf(x1, 0.f); y1 = fmaxf(y1, 0.f);
        }
        if (z0) { x0 = 0.f; y0 = 0.f; }
        if (z1) { x1 = 0.f; y1 = 0.f; }
        float hx0 = __bfloat162float(__float2bfloat16_rn(x0));
        float hy0 = __bfloat162float(__float2bfloat16_rn(y0));
        float hx1 = __bfloat162float(__float2bfloat16_rn(x1));
        float hy1 = __bfloat162float(__float2bfloat16_rn(y1));
        uint32_t o0 = (uint32_t)rA * SROW + (uint32_t)c * 2;
        uint32_t o1 = (uint32_t)(rA + 8) * SROW + (uint32_t)c * 2;
        *(uint32_t*)(smem + SA_HI + o0) = pack_bf2(hx0, hy0);
        *(uint32_t*)(smem + SA_LO + o0) = pack_bf2(x0 - hx0, y0 - hy0);
        *(uint32_t*)(smem + SA_HI + o1) = pack_bf2(hx1, hy1);
        *(uint32_t*)(smem + SA_LO + o1) = pack_bf2(x1 - hx1, y1 - hy1);
    }
}

// ---------------------------------------------------------------------------
// PERSISTENT phi kernel: W1 hi/lo resident; per tile: cp.async-staged A,
// convert -> combined 3-term MMA -> relu h -> segment reduce (sorted batch).
// ---------------------------------------------------------------------------
__global__ __launch_bounds__(NT, 1) void phi_seg_kernel(
    const float* __restrict__ ins, const int* __restrict__ batch,
    const __nv_bfloat16* __restrict__ Whi, const __nv_bfloat16* __restrict__ Wlo,
    const float* __restrict__ bias, int nrows, int ntiles)
{
    extern __shared__ __align__(16) char smem[];
    const uint32_t sbase = smem_u32(smem);
    const int tid = threadIdx.x, wid = tid >> 5, lane = tid & 31;

    // prologue prefetch of first tile
    {
        int t = blockIdx.x;
        if (t < ntiles) {
            long long row0 = (long long)t * TILE;
            for (int idx = tid; idx < 4096; idx += NT) {
                int r = idx >> 5, c = idx & 31;
                long long gr = row0 + r;
                cp16(sbase + STAGE + (uint32_t)idx * 16u,
                     ins + gr * D + c * 4, (gr < nrows) ? 16 : 0);
            }
            if (tid < 32) {
                long long r0 = row0 + tid * 4;
                long long rem = (long long)nrows - r0;
                int sz = rem >= 4 ? 16 : (rem > 0 ? (int)rem * 4 : 0);
                cp16(sbase + PSEG0 + (uint32_t)tid * 16u, batch + r0, sz);
            }
        }
        cp_commit();
    }
    load_W_pair(smem, Whi, Wlo, tid);
    if (tid < D) ((float*)(smem + PBIAS))[tid] = bias[tid];

    int buf = 0;
    for (int t = blockIdx.x; t < ntiles; t += gridDim.x) {
        cp_wait0();
        __syncthreads();
        // convert staged fp32 -> bf16 hi/lo
        for (int idx = tid; idx < 4096; idx += NT) {
            int r = idx >> 5, c4 = idx & 31;
            float4 v = *(const float4*)(smem + STAGE + (uint32_t)r * 512u + (uint32_t)c4 * 16u);
            float hx = __bfloat162float(__float2bfloat16_rn(v.x));
            float hy = __bfloat162float(__float2bfloat16_rn(v.y));
            float hz = __bfloat162float(__float2bfloat16_rn(v.z));
            float hw = __bfloat162float(__float2bfloat16_rn(v.w));
            uint32_t off = (uint32_t)r * SROW + (uint32_t)c4 * 8;
            *(uint2*)(smem + SA_HI + off) = make_uint2(pack_bf2(hx, hy), pack_bf2(hz, hw));
            *(uint2*)(smem + SA_LO + off) =
                make_uint2(pack_bf2(v.x - hx, v.y - hy), pack_bf2(v.z - hz, v.w - hw));
        }
        __syncthreads();   // stage free -> prefetch next tile
        {
            int nt_ = t + gridDim.x;
            if (nt_ < ntiles) {
                long long row0n = (long long)nt_ * TILE;
                for (int idx = tid; idx < 4096; idx += NT) {
                    int r = idx >> 5, c = idx & 31;
                    long long gr = row0n + r;
                    cp16(sbase + STAGE + (uint32_t)idx * 16u,
                         ins + gr * D + c * 4, (gr < nrows) ? 16 : 0);
                }
                if (tid < 32) {
                    long long r0 = row0n + tid * 4;
                    long long rem = (long long)nrows - r0;
                    int sz = rem >= 4 ? 16 : (rem > 0 ? (int)rem * 4 : 0);
                    cp16(sbase + (buf ? PSEG0 : PSEG1) + (uint32_t)tid * 16u,
                         batch + r0, sz);
                }
            }
            cp_commit();
        }

        float acc[16][4];
#pragma unroll
        for (int i = 0; i < 16; i++)
#pragma unroll
            for (int j = 0; j < 4; j++) acc[i][j] = 0.f;
        gemm_pass3(sbase, acc, wid, lane);
        __syncthreads();   // A buffers free

        // h = relu(acc + b) into sH (reuses A region)
        float* sH = (float*)(smem + SA_HI);
        const float* sB = (const float*)(smem + PBIAS);
        {
            const int grp = lane >> 2, qp = lane & 3;
            const int rA = wid * 16 + grp;
#pragma unroll
            for (int nt = 0; nt < 16; nt++) {
                int c = nt * 8 + qp * 2;
                float b0 = sB[c], b1 = sB[c + 1];
                *(float2*)(sH + rA * 128 + c) =
                    make_float2(fmaxf(acc[nt][0] + b0, 0.f), fmaxf(acc[nt][1] + b1, 0.f));
                *(float2*)(sH + (rA + 8) * 128 + c) =
                    make_float2(fmaxf(acc[nt][2] + b0, 0.f), fmaxf(acc[nt][3] + b1, 0.f));
            }
        }
        __syncthreads();

        // segment reduce (sorted batch -> contiguous runs)
        const int* sSeg = (const int*)(smem + (buf ? PSEG1 : PSEG0));
        const int row0 = t * TILE;
        const int col = tid & (D - 1);
        const int rbeg = (tid >> 7) * (TILE / 2);
        int cur = (row0 + rbeg < nrows) ? sSeg[rbeg] : -1;
        float run = 0.f, cnt = 0.f;
        for (int r = rbeg; r < rbeg + TILE / 2; r++) {
            int s = (row0 + r < nrows) ? sSeg[r] : -1;
            if (s != cur) {
                if (cur >= 0) {
                    atomicAdd(&g_segsum[(size_t)cur * D + col], run);
                    if (col == 0) atomicAdd(&g_cnt[cur], cnt);
                }
                cur = s; run = 0.f; cnt = 0.f;
            }
            run += sH[r * 128 + col];
            cnt += 1.f;
        }
        if (cur >= 0) {
            atomicAdd(&g_segsum[(size_t)cur * D + col], run);
            if (col == 0) atomicAdd(&g_cnt[cur], cnt);
        }
        __syncthreads();   // sH read done before next convert overwrites
        buf ^= 1;
    }
}

// ---------------------------------------------------------------------------
// fused small path: u = mean@phiW2+b2 (zero-empty); v = relu(u@rhoW1+rb1);
// out = v@rhoW2+rb2. W hi/lo pair resident per stage, single combined pass.
// ---------------------------------------------------------------------------
__global__ __launch_bounds__(NT, 1) void rho_fused_kernel(
    const __nv_bfloat16* __restrict__ W2hi, const __nv_bfloat16* __restrict__ W2lo,
    const __nv_bfloat16* __restrict__ R1hi, const __nv_bfloat16* __restrict__ R1lo,
    const __nv_bfloat16* __restrict__ R2hi, const __nv_bfloat16* __restrict__ R2lo,
    const float* __restrict__ b2, const float* __restrict__ rb1,
    const float* __restrict__ rb2, float* __restrict__ outp, int nrows)
{
    extern __shared__ __align__(16) char smem[];
    const uint32_t sbase = smem_u32(smem);
    const int tid = threadIdx.x, wid = tid >> 5, lane = tid & 31;
    const int row0 = blockIdx.x * TILE;

    float* sB = (float*)(smem + RBIAS);
    float* sCnt = (float*)(smem + RCNT);
    if (tid < D) {
        sB[tid] = b2[tid];
        sB[128 + tid] = rb1[tid];
        sB[256 + tid] = rb2[tid];
    }
    if (tid < TILE) {
        int gr = row0 + tid;
        sCnt[tid] = (gr < nrows) ? g_cnt[gr] : 0.f;
    }
    load_W_pair(smem, W2hi, W2lo, tid);
    __syncthreads();

    // A tile: mean = segsum / max(cnt,1), split hi/lo
    for (int idx = tid; idx < TILE * 32; idx += NT) {
        int r = idx >> 5, c4 = idx & 31;
        float4 v = make_float4(0.f, 0.f, 0.f, 0.f);
        int gr = row0 + r;
        if (gr < nrows) {
            v = *(const float4*)(g_segsum + (size_t)gr * D + c4 * 4);
            float s = 1.f / fmaxf(sCnt[r], 1.f);
            v.x *= s; v.y *= s; v.z *= s; v.w *= s;
        }
        float hx = __bfloat162float(__float2bfloat16_rn(v.x));
        float hy = __bfloat162float(__float2bfloat16_rn(v.y));
        float hz = __bfloat162float(__float2bfloat16_rn(v.z));
        float hw = __bfloat162float(__float2bfloat16_rn(v.w));
        uint32_t off = (uint32_t)r * SROW + (uint32_t)c4 * 8;
        *(uint2*)(smem + SA_HI + off) = make_uint2(pack_bf2(hx, hy), pack_bf2(hz, hw));
        *(uint2*)(smem + SA_LO + off) =
            make_uint2(pack_bf2(v.x - hx, v.y - hy), pack_bf2(v.z - hz, v.w - hw));
    }
    __syncthreads();

    float acc[16][4];
    // ---- stage 1: u = mean@phiW2 + b2 (zero empty rows) ----
#pragma unroll
    for (int i = 0; i < 16; i++)
#pragma unroll
        for (int j = 0; j < 4; j++) acc[i][j] = 0.f;
    gemm_pass3(sbase, acc, wid, lane);
    __syncthreads();
    frag_store_A(smem, acc, sB, sCnt, false, true, wid, lane);
    load_W_pair(smem, R1hi, R1lo, tid);
    __syncthreads();

    // ---- stage 2: v = relu(u@rhoW1 + rb1) ----
#pragma unroll
    for (int i = 0; i < 16; i++)
#pragma unroll
        for (int j = 0; j < 4; j++) acc[i][j] = 0.f;
    gemm_pass3(sbase, acc, wid, lane);
    __syncthreads();
    frag_store_A(smem, acc, sB + 128, sCnt, true, false, wid, lane);
    load_W_pair(smem, R2hi, R2lo, tid);
    __syncthreads();

    // ---- stage 3: out = v@rhoW2 + rb2 ----
#pragma unroll
    for (int i = 0; i < 16; i++)
#pragma unroll
        for (int j = 0; j < 4; j++) acc[i][j] = 0.f;
    gemm_pass3(sbase, acc, wid, lane);
    {
        const int grp = lane >> 2, qp = lane & 3;
        const int rA = wid * 16 + grp;
        int gr0 = row0 + rA, gr1 = row0 + rA + 8;
#pragma unroll
        for (int nt = 0; nt < 16; nt++) {
            int c = nt * 8 + qp * 2;
            float b0 = sB[256 + c], b1 = sB[256 + c + 1];
            if (gr0 < nrows)
                *(float2*)(outp + (size_t)gr0 * D + c) =
                    make_float2(acc[nt][0] + b0, acc[nt][1] + b1);
            if (gr1 < nrows)
                *(float2*)(outp + (size_t)gr1 * D + c) =
                    make_float2(acc[nt][2] + b0, acc[nt][3] + b1);
        }
    }
}

// ---------------------------------------------------------------------------
extern "C" void kernel_launch(void* const* d_in, const int* in_sizes, int n_in,
                              void* d_out, int out_size)
{
    const float* ins    = (const float*)d_in[0];
    const int*   batch  = (const int*)d_in[1];
    const float* phi_W1 = (const float*)d_in[3];
    const float* phi_b1 = (const float*)d_in[4];
    const float* phi_W2 = (const float*)d_in[5];
    const float* phi_b2 = (const float*)d_in[6];
    const float* rho_W1 = (const float*)d_in[7];
    const float* rho_b1 = (const float*)d_in[8];
    const float* rho_W2 = (const float*)d_in[9];
    const float* rho_b2 = (const float*)d_in[10];
    float* out = (float*)d_out;

    const int N = in_sizes[0] / D;
    const int ntiles = (N + TILE - 1) / TILE;

    cudaFuncSetAttribute(phi_seg_kernel, cudaFuncAttributeMaxDynamicSharedMemorySize, PHI_SMEM);
    cudaFuncSetAttribute(rho_fused_kernel, cudaFuncAttributeMaxDynamicSharedMemorySize, RHO_SMEM);

    void *p_whi = nullptr, *p_wlo = nullptr;
    cudaGetSymbolAddress(&p_whi, g_Whi);
    cudaGetSymbolAddress(&p_wlo, g_Wlo);
    const __nv_bfloat16* Whi = (const __nv_bfloat16*)p_whi;
    const __nv_bfloat16* Wlo = (const __nv_bfloat16*)p_wlo;

    int zgrid = (NSEG * D + NT - 1) / NT;
    zero_kernel<<<zgrid, NT>>>();
    prep_kernel<<<(4 * D * D + NT - 1) / NT, NT>>>(phi_W1, phi_W2, rho_W1, rho_W2);

    int gphi = 148;
    if (gphi > ntiles) gphi = ntiles;
    phi_seg_kernel<<<gphi, NT, PHI_SMEM>>>(ins, batch,
        Whi + 0 * D * D, Wlo + 0 * D * D, phi_b1, N, ntiles);

    int g2 = (NSEG + TILE - 1) / TILE;
    rho_fused_kernel<<<g2, NT, RHO_SMEM>>>(
        Whi + 1 * D * D, Wlo + 1 * D * D,
        Whi + 2 * D * D, Wlo + 2 * D * D,
        Whi + 3 * D * D, Wlo + 3 * D * D,
        phi_b2, rho_b1, rho_b2, out, NSEG);
}

// round 6
// speedup vs baseline: 3.3463x; 1.2312x over previous
#include <cuda_runtime.h>
#include <cuda_bf16.h>
#include <cstdint>

#define D 128
#define TILE 128
#define NSEG 50000
#define NT 512

// ---------------- device scratch ----------------
__device__ __align__(16) float g_segsum[NSEG * D];
__device__ __align__(16) float g_cnt[NSEG];
// transposed weights Wt[n][k] = W[k][n], bf16 hi/lo split, 4 matrices
__device__ __align__(16) __nv_bfloat16 g_Whi[4][D * D];
__device__ __align__(16) __nv_bfloat16 g_Wlo[4][D * D];

// ---------------- smem layout (bytes) ----------------
#define SROW 272u
#define SW_HI 0u
#define SW_LO 34816u
#define SA_HI 69632u
#define SA_LO 104448u
// phi persistent extras
#define STAGE 139264u      // fp32 A staging, 65536 B
#define PBIAS 204800u      // 512 B
#define PSEG0 205312u      // 512 B
#define PSEG1 205824u      // 512 B
#define PHI_SMEM 206336u
// rho extras
#define RBIAS 139264u      // 3 x 512 B
#define RCNT  140800u      // 512 B
#define RHO_SMEM 141312u

__device__ __forceinline__ uint32_t smem_u32(const void* p) {
    return (uint32_t)__cvta_generic_to_shared(p);
}

#define LDSM_X4(r0, r1, r2, r3, addr)                                         \
    asm volatile("ldmatrix.sync.aligned.m8n8.x4.shared.b16 {%0,%1,%2,%3}, [%4];" \
                 : "=r"(r0), "=r"(r1), "=r"(r2), "=r"(r3) : "r"(addr))

#define MMA16816(d, a0, a1, a2, a3, b0, b1)                                   \
    asm volatile("mma.sync.aligned.m16n8k16.row.col.f32.bf16.bf16.f32 "       \
                 "{%0,%1,%2,%3},{%4,%5,%6,%7},{%8,%9},{%0,%1,%2,%3};"         \
                 : "+f"((d)[0]), "+f"((d)[1]), "+f"((d)[2]), "+f"((d)[3])     \
                 : "r"(a0), "r"(a1), "r"(a2), "r"(a3), "r"(b0), "r"(b1))

__device__ __forceinline__ uint32_t pack_bf2(float x, float y) {
    __nv_bfloat162 t = __floats2bfloat162_rn(x, y);
    return *(uint32_t*)&t;
}
__device__ __forceinline__ void cp16(uint32_t dst, const void* src, int bytes) {
    asm volatile("cp.async.cg.shared.global [%0], [%1], 16, %2;"
                 :: "r"(dst), "l"(src), "r"(bytes) : "memory");
}
__device__ __forceinline__ void cp_commit() {
    asm volatile("cp.async.commit_group;" ::: "memory");
}
__device__ __forceinline__ void cp_wait0() {
    asm volatile("cp.async.wait_group 0;" ::: "memory");
}

// ---------------------------------------------------------------------------
__global__ void prep_kernel(const float* __restrict__ W0, const float* __restrict__ W1,
                            const float* __restrict__ W2, const float* __restrict__ W3) {
    int i = blockIdx.x * blockDim.x + threadIdx.x;
    if (i >= 4 * D * D) return;
    const float* Ws[4] = {W0, W1, W2, W3};
    int mat = i >> 14;
    int e = i & (D * D - 1);
    int n = e >> 7, k = e & (D - 1);
    float w = Ws[mat][k * D + n];
    __nv_bfloat16 hi = __float2bfloat16_rn(w);
    float lo = w - __bfloat162float(hi);
    g_Whi[mat][n * D + k] = hi;
    g_Wlo[mat][n * D + k] = __float2bfloat16_rn(lo);
}

__global__ void zero_kernel() {
    int i = blockIdx.x * blockDim.x + threadIdx.x;
    if (i < NSEG * D) g_segsum[i] = 0.f;
    if (i < NSEG) g_cnt[i] = 0.f;
}

// ---------------------------------------------------------------------------
__device__ __forceinline__ void load_W_pair(char* smem,
                                            const __nv_bfloat16* __restrict__ Whi,
                                            const __nv_bfloat16* __restrict__ Wlo,
                                            int tid) {
    for (int idx = tid; idx < TILE * 16; idx += NT) {
        int r = idx >> 4, ch = idx & 15;
        uint32_t off = (uint32_t)r * SROW + (uint32_t)ch * 16;
        *(uint4*)(smem + SW_HI + off) = *(const uint4*)(Whi + r * D + ch * 8);
        *(uint4*)(smem + SW_LO + off) = *(const uint4*)(Wlo + r * D + ch * 8);
    }
}

// combined 3-term pass: acc += Ahi*Whi + Alo*Whi + Ahi*Wlo.
// 16 warps: wm = wid&7 (M tile of 16 rows), wn = wid>>3 (N half of 64 cols).
// Per warp: acc[8][4] = 16 rows x 64 cols.
__device__ __forceinline__ void gemm_pass3(uint32_t sbase, float (*acc)[4],
                                           int wm, int wn, int lane) {
    const uint32_t aRow = (uint32_t)(wm * 16 + (lane & 15));
    const uint32_t aColB = (uint32_t)((lane >> 4) * 16);
    uint32_t aHi = sbase + SA_HI + aRow * SROW + aColB;
    uint32_t aLo = sbase + SA_LO + aRow * SROW + aColB;
    const uint32_t bRow = (uint32_t)((lane & 7) + ((lane & 16) ? 8 : 0));
    const uint32_t bColB = (uint32_t)(((lane & 8) ? 8 : 0) * 2);
    // N-half offset: 64 output cols = 64 rows of Wt = 4 blocks of 16
    const uint32_t bHi0 = sbase + SW_HI + (bRow + (uint32_t)wn * 64u) * SROW + bColB;
    const uint32_t bLo0 = sbase + SW_LO + (bRow + (uint32_t)wn * 64u) * SROW + bColB;

#pragma unroll 1
    for (int k = 0; k < 8; k++) {
        uint32_t ah0, ah1, ah2, ah3, al0, al1, al2, al3;
        LDSM_X4(ah0, ah1, ah2, ah3, aHi);
        LDSM_X4(al0, al1, al2, al3, aLo);
        uint32_t bh = bHi0 + (uint32_t)k * 32;
        uint32_t bl = bLo0 + (uint32_t)k * 32;
        uint32_t w0, w1, w2, w3;
        LDSM_X4(w0, w1, w2, w3, bh);
#pragma unroll
        for (int nt2 = 0; nt2 < 4; nt2++) {
            uint32_t v0, v1, v2, v3, n0, n1, n2, n3;
            LDSM_X4(v0, v1, v2, v3, bl);
            if (nt2 < 3) { LDSM_X4(n0, n1, n2, n3, bh + 16u * SROW); }
            MMA16816(acc[2 * nt2],     ah0, ah1, ah2, ah3, w0, w1);
            MMA16816(acc[2 * nt2 + 1], ah0, ah1, ah2, ah3, w2, w3);
            MMA16816(acc[2 * nt2],     al0, al1, al2, al3, w0, w1);
            MMA16816(acc[2 * nt2 + 1], al0, al1, al2, al3, w2, w3);
            MMA16816(acc[2 * nt2],     ah0, ah1, ah2, ah3, v0, v1);
            MMA16816(acc[2 * nt2 + 1], ah0, ah1, ah2, ah3, v2, v3);
            if (nt2 < 3) { w0 = n0; w1 = n1; w2 = n2; w3 = n3; }
            bh += 16u * SROW;
            bl += 16u * SROW;
        }
        aHi += 32;
        aLo += 32;
    }
}

// fragments (+bias, opt relu, opt zero-empty) back to A smem as bf16 hi/lo
__device__ __forceinline__ void frag_store_A(char* smem, float (*acc)[4],
                                             const float* bias, const float* sCnt,
                                             bool relu, bool zeroE,
                                             int wm, int wn, int lane) {
    const int grp = lane >> 2, qp = lane & 3;
    const int rA = wm * 16 + grp;
    bool z0 = zeroE && (sCnt[rA] <= 0.f);
    bool z1 = zeroE && (sCnt[rA + 8] <= 0.f);
#pragma unroll
    for (int nt = 0; nt < 8; nt++) {
        int c = wn * 64 + nt * 8 + qp * 2;
        float b0 = bias[c], b1 = bias[c + 1];
        float x0 = acc[nt][0] + b0, y0 = acc[nt][1] + b1;
        float x1 = acc[nt][2] + b0, y1 = acc[nt][3] + b1;
        if (relu) {
            x0 = fmaxf(x0, 0.f); y0 = fmaxf(y0, 0.f);
            x1 = fmaxf(x1, 0.f); y1 = fmaxf(y1, 0.f);
        }
        if (z0) { x0 = 0.f; y0 = 0.f; }
        if (z1) { x1 = 0.f; y1 = 0.f; }
        float hx0 = __bfloat162float(__float2bfloat16_rn(x0));
        float hy0 = __bfloat162float(__float2bfloat16_rn(y0));
        float hx1 = __bfloat162float(__float2bfloat16_rn(x1));
        float hy1 = __bfloat162float(__float2bfloat16_rn(y1));
        uint32_t o0 = (uint32_t)rA * SROW + (uint32_t)c * 2;
        uint32_t o1 = (uint32_t)(rA + 8) * SROW + (uint32_t)c * 2;
        *(uint32_t*)(smem + SA_HI + o0) = pack_bf2(hx0, hy0);
        *(uint32_t*)(smem + SA_LO + o0) = pack_bf2(x0 - hx0, y0 - hy0);
        *(uint32_t*)(smem + SA_HI + o1) = pack_bf2(hx1, hy1);
        *(uint32_t*)(smem + SA_LO + o1) = pack_bf2(x1 - hx1, y1 - hy1);
    }
}

// ---------------------------------------------------------------------------
// PERSISTENT phi kernel (512 threads): W1 hi/lo resident; per tile:
// cp.async-staged A -> convert -> 3-term MMA -> relu h -> segment reduce.
// ---------------------------------------------------------------------------
__global__ __launch_bounds__(NT, 1) void phi_seg_kernel(
    const float* __restrict__ ins, const int* __restrict__ batch,
    const __nv_bfloat16* __restrict__ Whi, const __nv_bfloat16* __restrict__ Wlo,
    const float* __restrict__ bias, int nrows, int ntiles)
{
    extern __shared__ __align__(16) char smem[];
    const uint32_t sbase = smem_u32(smem);
    const int tid = threadIdx.x;
    const int wid = tid >> 5, lane = tid & 31;
    const int wm = wid & 7, wn = wid >> 3;

    // prologue prefetch of first tile
    {
        int t = blockIdx.x;
        if (t < ntiles) {
            long long row0 = (long long)t * TILE;
            for (int idx = tid; idx < 4096; idx += NT) {
                int r = idx >> 5, c = idx & 31;
                long long gr = row0 + r;
                cp16(sbase + STAGE + (uint32_t)idx * 16u,
                     ins + gr * D + c * 4, (gr < nrows) ? 16 : 0);
            }
            if (tid < 32) {
                long long r0 = row0 + tid * 4;
                long long rem = (long long)nrows - r0;
                int sz = rem >= 4 ? 16 : (rem > 0 ? (int)rem * 4 : 0);
                cp16(sbase + PSEG0 + (uint32_t)tid * 16u, batch + r0, sz);
            }
        }
        cp_commit();
    }
    load_W_pair(smem, Whi, Wlo, tid);
    if (tid < D) ((float*)(smem + PBIAS))[tid] = bias[tid];

    int buf = 0;
    for (int t = blockIdx.x; t < ntiles; t += gridDim.x) {
        cp_wait0();
        __syncthreads();
        // convert staged fp32 -> bf16 hi/lo
        for (int idx = tid; idx < 4096; idx += NT) {
            int r = idx >> 5, c4 = idx & 31;
            float4 v = *(const float4*)(smem + STAGE + (uint32_t)r * 512u + (uint32_t)c4 * 16u);
            float hx = __bfloat162float(__float2bfloat16_rn(v.x));
            float hy = __bfloat162float(__float2bfloat16_rn(v.y));
            float hz = __bfloat162float(__float2bfloat16_rn(v.z));
            float hw = __bfloat162float(__float2bfloat16_rn(v.w));
            uint32_t off = (uint32_t)r * SROW + (uint32_t)c4 * 8;
            *(uint2*)(smem + SA_HI + off) = make_uint2(pack_bf2(hx, hy), pack_bf2(hz, hw));
            *(uint2*)(smem + SA_LO + off) =
                make_uint2(pack_bf2(v.x - hx, v.y - hy), pack_bf2(v.z - hz, v.w - hw));
        }
        __syncthreads();   // stage free -> prefetch next tile
        {
            int nt_ = t + gridDim.x;
            if (nt_ < ntiles) {
                long long row0n = (long long)nt_ * TILE;
                for (int idx = tid; idx < 4096; idx += NT) {
                    int r = idx >> 5, c = idx & 31;
                    long long gr = row0n + r;
                    cp16(sbase + STAGE + (uint32_t)idx * 16u,
                         ins + gr * D + c * 4, (gr < nrows) ? 16 : 0);
                }
                if (tid < 32) {
                    long long r0 = row0n + tid * 4;
                    long long rem = (long long)nrows - r0;
                    int sz = rem >= 4 ? 16 : (rem > 0 ? (int)rem * 4 : 0);
                    cp16(sbase + (buf ? PSEG0 : PSEG1) + (uint32_t)tid * 16u,
                         batch + r0, sz);
                }
            }
            cp_commit();
        }

        float acc[8][4];
#pragma unroll
        for (int i = 0; i < 8; i++)
#pragma unroll
            for (int j = 0; j < 4; j++) acc[i][j] = 0.f;
        gemm_pass3(sbase, acc, wm, wn, lane);
        __syncthreads();   // A buffers free

        // h = relu(acc + b) into sH (reuses A region)
        float* sH = (float*)(smem + SA_HI);
        const float* sB = (const float*)(smem + PBIAS);
        {
            const int grp = lane >> 2, qp = lane & 3;
            const int rA = wm * 16 + grp;
#pragma unroll
            for (int nt = 0; nt < 8; nt++) {
                int c = wn * 64 + nt * 8 + qp * 2;
                float b0 = sB[c], b1 = sB[c + 1];
                *(float2*)(sH + rA * 128 + c) =
                    make_float2(fmaxf(acc[nt][0] + b0, 0.f), fmaxf(acc[nt][1] + b1, 0.f));
                *(float2*)(sH + (rA + 8) * 128 + c) =
                    make_float2(fmaxf(acc[nt][2] + b0, 0.f), fmaxf(acc[nt][3] + b1, 0.f));
            }
        }
        __syncthreads();

        // segment reduce (sorted batch -> contiguous runs), 4 quarters of 32 rows
        const int* sSeg = (const int*)(smem + (buf ? PSEG1 : PSEG0));
        const int row0 = t * TILE;
        const int col = tid & (D - 1);
        const int rbeg = (tid >> 7) * 32;
        int cur = (row0 + rbeg < nrows) ? sSeg[rbeg] : -1;
        float run = 0.f, cnt = 0.f;
        for (int r = rbeg; r < rbeg + 32; r++) {
            int s = (row0 + r < nrows) ? sSeg[r] : -1;
            if (s != cur) {
                if (cur >= 0) {
                    atomicAdd(&g_segsum[(size_t)cur * D + col], run);
                    if (col == 0) atomicAdd(&g_cnt[cur], cnt);
                }
                cur = s; run = 0.f; cnt = 0.f;
            }
            run += sH[r * 128 + col];
            cnt += 1.f;
        }
        if (cur >= 0) {
            atomicAdd(&g_segsum[(size_t)cur * D + col], run);
            if (col == 0) atomicAdd(&g_cnt[cur], cnt);
        }
        __syncthreads();   // sH read done before next convert overwrites
        buf ^= 1;
    }
}

// ---------------------------------------------------------------------------
// fused small path (512 threads): u = mean@phiW2+b2 (zero-empty);
// v = relu(u@rhoW1+rb1); out = v@rhoW2+rb2.
// ---------------------------------------------------------------------------
__global__ __launch_bounds__(NT, 1) void rho_fused_kernel(
    const __nv_bfloat16* __restrict__ W2hi, const __nv_bfloat16* __restrict__ W2lo,
    const __nv_bfloat16* __restrict__ R1hi, const __nv_bfloat16* __restrict__ R1lo,
    const __nv_bfloat16* __restrict__ R2hi, const __nv_bfloat16* __restrict__ R2lo,
    const float* __restrict__ b2, const float* __restrict__ rb1,
    const float* __restrict__ rb2, float* __restrict__ outp, int nrows)
{
    extern __shared__ __align__(16) char smem[];
    const uint32_t sbase = smem_u32(smem);
    const int tid = threadIdx.x;
    const int wid = tid >> 5, lane = tid & 31;
    const int wm = wid & 7, wn = wid >> 3;
    const int row0 = blockIdx.x * TILE;

    float* sB = (float*)(smem + RBIAS);
    float* sCnt = (float*)(smem + RCNT);
    if (tid < D) {
        sB[tid] = b2[tid];
        sB[128 + tid] = rb1[tid];
        sB[256 + tid] = rb2[tid];
    }
    if (tid < TILE) {
        int gr = row0 + tid;
        sCnt[tid] = (gr < nrows) ? g_cnt[gr] : 0.f;
    }
    load_W_pair(smem, W2hi, W2lo, tid);
    __syncthreads();

    // A tile: mean = segsum / max(cnt,1), split hi/lo
    for (int idx = tid; idx < TILE * 32; idx += NT) {
        int r = idx >> 5, c4 = idx & 31;
        float4 v = make_float4(0.f, 0.f, 0.f, 0.f);
        int gr = row0 + r;
        if (gr < nrows) {
            v = *(const float4*)(g_segsum + (size_t)gr * D + c4 * 4);
            float s = 1.f / fmaxf(sCnt[r], 1.f);
            v.x *= s; v.y *= s; v.z *= s; v.w *= s;
        }
        float hx = __bfloat162float(__float2bfloat16_rn(v.x));
        float hy = __bfloat162float(__float2bfloat16_rn(v.y));
        float hz = __bfloat162float(__float2bfloat16_rn(v.z));
        float hw = __bfloat162float(__float2bfloat16_rn(v.w));
        uint32_t off = (uint32_t)r * SROW + (uint32_t)c4 * 8;
        *(uint2*)(smem + SA_HI + off) = make_uint2(pack_bf2(hx, hy), pack_bf2(hz, hw));
        *(uint2*)(smem + SA_LO + off) =
            make_uint2(pack_bf2(v.x - hx, v.y - hy), pack_bf2(v.z - hz, v.w - hw));
    }
    __syncthreads();

    float acc[8][4];
    // ---- stage 1: u = mean@phiW2 + b2 (zero empty rows) ----
#pragma unroll
    for (int i = 0; i < 8; i++)
#pragma unroll
        for (int j = 0; j < 4; j++) acc[i][j] = 0.f;
    gemm_pass3(sbase, acc, wm, wn, lane);
    __syncthreads();
    frag_store_A(smem, acc, sB, sCnt, false, true, wm, wn, lane);
    load_W_pair(smem, R1hi, R1lo, tid);
    __syncthreads();

    // ---- stage 2: v = relu(u@rhoW1 + rb1) ----
#pragma unroll
    for (int i = 0; i < 8; i++)
#pragma unroll
        for (int j = 0; j < 4; j++) acc[i][j] = 0.f;
    gemm_pass3(sbase, acc, wm, wn, lane);
    __syncthreads();
    frag_store_A(smem, acc, sB + 128, sCnt, true, false, wm, wn, lane);
    load_W_pair(smem, R2hi, R2lo, tid);
    __syncthreads();

    // ---- stage 3: out = v@rhoW2 + rb2 ----
#pragma unroll
    for (int i = 0; i < 8; i++)
#pragma unroll
        for (int j = 0; j < 4; j++) acc[i][j] = 0.f;
    gemm_pass3(sbase, acc, wm, wn, lane);
    {
        const int grp = lane >> 2, qp = lane & 3;
        const int rA = wm * 16 + grp;
        int gr0 = row0 + rA, gr1 = row0 + rA + 8;
#pragma unroll
        for (int nt = 0; nt < 8; nt++) {
            int c = wn * 64 + nt * 8 + qp * 2;
            float b0 = sB[256 + c], b1 = sB[256 + c + 1];
            if (gr0 < nrows)
                *(float2*)(outp + (size_t)gr0 * D + c) =
                    make_float2(acc[nt][0] + b0, acc[nt][1] + b1);
            if (gr1 < nrows)
                *(float2*)(outp + (size_t)gr1 * D + c) =
                    make_float2(acc[nt][2] + b0, acc[nt][3] + b1);
        }
    }
}

// ---------------------------------------------------------------------------
extern "C" void kernel_launch(void* const* d_in, const int* in_sizes, int n_in,
                              void* d_out, int out_size)
{
    const float* ins    = (const float*)d_in[0];
    const int*   batch  = (const int*)d_in[1];
    const float* phi_W1 = (const float*)d_in[3];
    const float* phi_b1 = (const float*)d_in[4];
    const float* phi_W2 = (const float*)d_in[5];
    const float* phi_b2 = (const float*)d_in[6];
    const float* rho_W1 = (const float*)d_in[7];
    const float* rho_b1 = (const float*)d_in[8];
    const float* rho_W2 = (const float*)d_in[9];
    const float* rho_b2 = (const float*)d_in[10];
    float* out = (float*)d_out;

    const int N = in_sizes[0] / D;
    const int ntiles = (N + TILE - 1) / TILE;

    cudaFuncSetAttribute(phi_seg_kernel, cudaFuncAttributeMaxDynamicSharedMemorySize, PHI_SMEM);
    cudaFuncSetAttribute(rho_fused_kernel, cudaFuncAttributeMaxDynamicSharedMemorySize, RHO_SMEM);

    void *p_whi = nullptr, *p_wlo = nullptr;
    cudaGetSymbolAddress(&p_whi, g_Whi);
    cudaGetSymbolAddress(&p_wlo, g_Wlo);
    const __nv_bfloat16* Whi = (const __nv_bfloat16*)p_whi;
    const __nv_bfloat16* Wlo = (const __nv_bfloat16*)p_wlo;

    int zgrid = (NSEG * D + 255) / 256;
    zero_kernel<<<zgrid, 256>>>();
    prep_kernel<<<(4 * D * D + 255) / 256, 256>>>(phi_W1, phi_W2, rho_W1, rho_W2);

    int gphi = 148;
    if (gphi > ntiles) gphi = ntiles;
    phi_seg_kernel<<<gphi, NT, PHI_SMEM>>>(ins, batch,
        Whi + 0 * D * D, Wlo + 0 * D * D, phi_b1, N, ntiles);

    int g2 = (NSEG + TILE - 1) / TILE;
    rho_fused_kernel<<<g2, NT, RHO_SMEM>>>(
        Whi + 1 * D * D, Wlo + 1 * D * D,
        Whi + 2 * D * D, Wlo + 2 * D * D,
        Whi + 3 * D * D, Wlo + 3 * D * D,
        phi_b2, rho_b1, rho_b2, out, NSEG);
}

// round 7
// speedup vs baseline: 3.6303x; 1.0849x over previous
#include <cuda_runtime.h>
#include <cuda_bf16.h>
#include <cstdint>

#define D 128
#define TILE 128
#define NSEG 50000
#define NT 1024

// ---------------- device scratch ----------------
__device__ __align__(16) float g_segsum[NSEG * D];
__device__ __align__(16) float g_cnt[NSEG];
// transposed weights Wt[n][k] = W[k][n], bf16 hi/lo split, 4 matrices
__device__ __align__(16) __nv_bfloat16 g_Whi[4][D * D];
__device__ __align__(16) __nv_bfloat16 g_Wlo[4][D * D];

// ---------------- smem layout (bytes) ----------------
#define SROW 272u
#define SW_HI 0u
#define SW_LO 34816u
#define SA_HI 69632u
#define SA_LO 104448u
// phi persistent extras
#define STAGE 139264u      // fp32 A staging, 65536 B
#define PBIAS 204800u      // 512 B
#define PSEG0 205312u      // 512 B
#define PSEG1 205824u      // 512 B
#define PHI_SMEM 206336u
// rho extras
#define RBIAS 139264u      // 3 x 512 B
#define RCNT  140800u      // 512 B
#define RHO_SMEM 141312u

__device__ __forceinline__ uint32_t smem_u32(const void* p) {
    return (uint32_t)__cvta_generic_to_shared(p);
}

#define LDSM_X4(r0, r1, r2, r3, addr)                                         \
    asm volatile("ldmatrix.sync.aligned.m8n8.x4.shared.b16 {%0,%1,%2,%3}, [%4];" \
                 : "=r"(r0), "=r"(r1), "=r"(r2), "=r"(r3) : "r"(addr))

#define MMA16816(d, a0, a1, a2, a3, b0, b1)                                   \
    asm volatile("mma.sync.aligned.m16n8k16.row.col.f32.bf16.bf16.f32 "       \
                 "{%0,%1,%2,%3},{%4,%5,%6,%7},{%8,%9},{%0,%1,%2,%3};"         \
                 : "+f"((d)[0]), "+f"((d)[1]), "+f"((d)[2]), "+f"((d)[3])     \
                 : "r"(a0), "r"(a1), "r"(a2), "r"(a3), "r"(b0), "r"(b1))

__device__ __forceinline__ uint32_t pack_bf2(float x, float y) {
    __nv_bfloat162 t = __floats2bfloat162_rn(x, y);
    return *(uint32_t*)&t;
}
__device__ __forceinline__ void cp16(uint32_t dst, const void* src, int bytes) {
    asm volatile("cp.async.cg.shared.global [%0], [%1], 16, %2;"
                 :: "r"(dst), "l"(src), "r"(bytes) : "memory");
}
__device__ __forceinline__ void cp_commit() {
    asm volatile("cp.async.commit_group;" ::: "memory");
}
__device__ __forceinline__ void cp_wait0() {
    asm volatile("cp.async.wait_group 0;" ::: "memory");
}

// ---------------------------------------------------------------------------
__global__ void prep_kernel(const float* __restrict__ W0, const float* __restrict__ W1,
                            const float* __restrict__ W2, const float* __restrict__ W3) {
    int i = blockIdx.x * blockDim.x + threadIdx.x;
    if (i >= 4 * D * D) return;
    const float* Ws[4] = {W0, W1, W2, W3};
    int mat = i >> 14;
    int e = i & (D * D - 1);
    int n = e >> 7, k = e & (D - 1);
    float w = Ws[mat][k * D + n];
    __nv_bfloat16 hi = __float2bfloat16_rn(w);
    float lo = w - __bfloat162float(hi);
    g_Whi[mat][n * D + k] = hi;
    g_Wlo[mat][n * D + k] = __float2bfloat16_rn(lo);
}

__global__ void zero_kernel() {
    int i = blockIdx.x * blockDim.x + threadIdx.x;
    if (i < NSEG * D) g_segsum[i] = 0.f;
    if (i < NSEG) g_cnt[i] = 0.f;
}

// ---------------------------------------------------------------------------
__device__ __forceinline__ void load_W_pair(char* smem,
                                            const __nv_bfloat16* __restrict__ Whi,
                                            const __nv_bfloat16* __restrict__ Wlo,
                                            int tid) {
    for (int idx = tid; idx < TILE * 16; idx += NT) {
        int r = idx >> 4, ch = idx & 15;
        uint32_t off = (uint32_t)r * SROW + (uint32_t)ch * 16;
        *(uint4*)(smem + SW_HI + off) = *(const uint4*)(Whi + r * D + ch * 8);
        *(uint4*)(smem + SW_LO + off) = *(const uint4*)(Wlo + r * D + ch * 8);
    }
}

// combined 3-term pass: acc += Ahi*Whi + Alo*Whi + Ahi*Wlo.
// 32 warps: wm = wid&7 (16 M-rows), wn = wid>>3 (32 N-cols quarter).
// Per warp: acc[4][4] = 16 rows x 32 cols.
__device__ __forceinline__ void gemm_pass3(uint32_t sbase, float (*acc)[4],
                                           int wm, int wn, int lane) {
    const uint32_t aRow = (uint32_t)(wm * 16 + (lane & 15));
    const uint32_t aColB = (uint32_t)((lane >> 4) * 16);
    uint32_t aHi = sbase + SA_HI + aRow * SROW + aColB;
    uint32_t aLo = sbase + SA_LO + aRow * SROW + aColB;
    const uint32_t bRow = (uint32_t)((lane & 7) + ((lane & 16) ? 8 : 0));
    const uint32_t bColB = (uint32_t)(((lane & 8) ? 8 : 0) * 2);
    // N-quarter offset: 32 output cols = 32 rows of Wt
    const uint32_t bHi0 = sbase + SW_HI + (bRow + (uint32_t)wn * 32u) * SROW + bColB;
    const uint32_t bLo0 = sbase + SW_LO + (bRow + (uint32_t)wn * 32u) * SROW + bColB;

#pragma unroll 1
    for (int k = 0; k < 8; k++) {
        uint32_t ah0, ah1, ah2, ah3, al0, al1, al2, al3;
        LDSM_X4(ah0, ah1, ah2, ah3, aHi);
        LDSM_X4(al0, al1, al2, al3, aLo);
        uint32_t bh = bHi0 + (uint32_t)k * 32;
        uint32_t bl = bLo0 + (uint32_t)k * 32;
#pragma unroll
        for (int nb = 0; nb < 2; nb++) {
            uint32_t w0, w1, w2, w3, v0, v1, v2, v3;
            LDSM_X4(w0, w1, w2, w3, bh);
            LDSM_X4(v0, v1, v2, v3, bl);
            MMA16816(acc[2 * nb],     ah0, ah1, ah2, ah3, w0, w1);
            MMA16816(acc[2 * nb + 1], ah0, ah1, ah2, ah3, w2, w3);
            MMA16816(acc[2 * nb],     al0, al1, al2, al3, w0, w1);
            MMA16816(acc[2 * nb + 1], al0, al1, al2, al3, w2, w3);
            MMA16816(acc[2 * nb],     ah0, ah1, ah2, ah3, v0, v1);
            MMA16816(acc[2 * nb + 1], ah0, ah1, ah2, ah3, v2, v3);
            bh += 16u * SROW;
            bl += 16u * SROW;
        }
        aHi += 32;
        aLo += 32;
    }
}

// fragments (+bias, opt relu, opt zero-empty) back to A smem as bf16 hi/lo
__device__ __forceinline__ void frag_store_A(char* smem, float (*acc)[4],
                                             const float* bias, const float* sCnt,
                                             bool relu, bool zeroE,
                                             int wm, int wn, int lane) {
    const int grp = lane >> 2, qp = lane & 3;
    const int rA = wm * 16 + grp;
    bool z0 = zeroE && (sCnt[rA] <= 0.f);
    bool z1 = zeroE && (sCnt[rA + 8] <= 0.f);
#pragma unroll
    for (int nt = 0; nt < 4; nt++) {
        int c = wn * 32 + nt * 8 + qp * 2;
        float b0 = bias[c], b1 = bias[c + 1];
        float x0 = acc[nt][0] + b0, y0 = acc[nt][1] + b1;
        float x1 = acc[nt][2] + b0, y1 = acc[nt][3] + b1;
        if (relu) {
            x0 = fmaxf(x0, 0.f); y0 = fmaxf(y0, 0.f);
            x1 = fmaxf(x1, 0.f); y1 = fmaxf(y1, 0.f);
        }
        if (z0) { x0 = 0.f; y0 = 0.f; }
        if (z1) { x1 = 0.f; y1 = 0.f; }
        float hx0 = __bfloat162float(__float2bfloat16_rn(x0));
        float hy0 = __bfloat162float(__float2bfloat16_rn(y0));
        float hx1 = __bfloat162float(__float2bfloat16_rn(x1));
        float hy1 = __bfloat162float(__float2bfloat16_rn(y1));
        uint32_t o0 = (uint32_t)rA * SROW + (uint32_t)c * 2;
        uint32_t o1 = (uint32_t)(rA + 8) * SROW + (uint32_t)c * 2;
        *(uint32_t*)(smem + SA_HI + o0) = pack_bf2(hx0, hy0);
        *(uint32_t*)(smem + SA_LO + o0) = pack_bf2(x0 - hx0, y0 - hy0);
        *(uint32_t*)(smem + SA_HI + o1) = pack_bf2(hx1, hy1);
        *(uint32_t*)(smem + SA_LO + o1) = pack_bf2(x1 - hx1, y1 - hy1);
    }
}

// ---------------------------------------------------------------------------
// PERSISTENT phi kernel (1024 threads): W1 hi/lo resident; per tile:
// cp.async-staged A -> convert -> 3-term MMA -> relu h -> segment reduce.
// ---------------------------------------------------------------------------
__global__ __launch_bounds__(NT, 1) void phi_seg_kernel(
    const float* __restrict__ ins, const int* __restrict__ batch,
    const __nv_bfloat16* __restrict__ Whi, const __nv_bfloat16* __restrict__ Wlo,
    const float* __restrict__ bias, int nrows, int ntiles)
{
    extern __shared__ __align__(16) char smem[];
    const uint32_t sbase = smem_u32(smem);
    const int tid = threadIdx.x;
    const int wid = tid >> 5, lane = tid & 31;
    const int wm = wid & 7, wn = wid >> 3;

    // prologue prefetch of first tile
    {
        int t = blockIdx.x;
        if (t < ntiles) {
            long long row0 = (long long)t * TILE;
            for (int idx = tid; idx < 4096; idx += NT) {
                int r = idx >> 5, c = idx & 31;
                long long gr = row0 + r;
                cp16(sbase + STAGE + (uint32_t)idx * 16u,
                     ins + gr * D + c * 4, (gr < nrows) ? 16 : 0);
            }
            if (tid < 32) {
                long long r0 = row0 + tid * 4;
                long long rem = (long long)nrows - r0;
                int sz = rem >= 4 ? 16 : (rem > 0 ? (int)rem * 4 : 0);
                cp16(sbase + PSEG0 + (uint32_t)tid * 16u, batch + r0, sz);
            }
        }
        cp_commit();
    }
    load_W_pair(smem, Whi, Wlo, tid);
    if (tid < D) ((float*)(smem + PBIAS))[tid] = bias[tid];

    int buf = 0;
    for (int t = blockIdx.x; t < ntiles; t += gridDim.x) {
        cp_wait0();
        __syncthreads();
        // convert staged fp32 -> bf16 hi/lo
        for (int idx = tid; idx < 4096; idx += NT) {
            int r = idx >> 5, c4 = idx & 31;
            float4 v = *(const float4*)(smem + STAGE + (uint32_t)r * 512u + (uint32_t)c4 * 16u);
            float hx = __bfloat162float(__float2bfloat16_rn(v.x));
            float hy = __bfloat162float(__float2bfloat16_rn(v.y));
            float hz = __bfloat162float(__float2bfloat16_rn(v.z));
            float hw = __bfloat162float(__float2bfloat16_rn(v.w));
            uint32_t off = (uint32_t)r * SROW + (uint32_t)c4 * 8;
            *(uint2*)(smem + SA_HI + off) = make_uint2(pack_bf2(hx, hy), pack_bf2(hz, hw));
            *(uint2*)(smem + SA_LO + off) =
                make_uint2(pack_bf2(v.x - hx, v.y - hy), pack_bf2(v.z - hz, v.w - hw));
        }
        __syncthreads();   // stage free -> prefetch next tile
        {
            int nt_ = t + gridDim.x;
            if (nt_ < ntiles) {
                long long row0n = (long long)nt_ * TILE;
                for (int idx = tid; idx < 4096; idx += NT) {
                    int r = idx >> 5, c = idx & 31;
                    long long gr = row0n + r;
                    cp16(sbase + STAGE + (uint32_t)idx * 16u,
                         ins + gr * D + c * 4, (gr < nrows) ? 16 : 0);
                }
                if (tid < 32) {
                    long long r0 = row0n + tid * 4;
                    long long rem = (long long)nrows - r0;
                    int sz = rem >= 4 ? 16 : (rem > 0 ? (int)rem * 4 : 0);
                    cp16(sbase + (buf ? PSEG0 : PSEG1) + (uint32_t)tid * 16u,
                         batch + r0, sz);
                }
            }
            cp_commit();
        }

        float acc[4][4];
#pragma unroll
        for (int i = 0; i < 4; i++)
#pragma unroll
            for (int j = 0; j < 4; j++) acc[i][j] = 0.f;
        gemm_pass3(sbase, acc, wm, wn, lane);
        __syncthreads();   // A buffers free

        // h = relu(acc + b) into sH (reuses A region)
        float* sH = (float*)(smem + SA_HI);
        const float* sB = (const float*)(smem + PBIAS);
        {
            const int grp = lane >> 2, qp = lane & 3;
            const int rA = wm * 16 + grp;
#pragma unroll
            for (int nt = 0; nt < 4; nt++) {
                int c = wn * 32 + nt * 8 + qp * 2;
                float b0 = sB[c], b1 = sB[c + 1];
                *(float2*)(sH + rA * 128 + c) =
                    make_float2(fmaxf(acc[nt][0] + b0, 0.f), fmaxf(acc[nt][1] + b1, 0.f));
                *(float2*)(sH + (rA + 8) * 128 + c) =
                    make_float2(fmaxf(acc[nt][2] + b0, 0.f), fmaxf(acc[nt][3] + b1, 0.f));
            }
        }
        __syncthreads();

        // segment reduce (sorted batch -> contiguous runs), 8 groups x 16 rows
        const int* sSeg = (const int*)(smem + (buf ? PSEG1 : PSEG0));
        const int row0 = t * TILE;
        const int col = tid & (D - 1);
        const int rbeg = (tid >> 7) * 16;
        int cur = (row0 + rbeg < nrows) ? sSeg[rbeg] : -1;
        float run = 0.f, cnt = 0.f;
        for (int r = rbeg; r < rbeg + 16; r++) {
            int s = (row0 + r < nrows) ? sSeg[r] : -1;
            if (s != cur) {
                if (cur >= 0) {
                    atomicAdd(&g_segsum[(size_t)cur * D + col], run);
                    if (col == 0) atomicAdd(&g_cnt[cur], cnt);
                }
                cur = s; run = 0.f; cnt = 0.f;
            }
            run += sH[r * 128 + col];
            cnt += 1.f;
        }
        if (cur >= 0) {
            atomicAdd(&g_segsum[(size_t)cur * D + col], run);
            if (col == 0) atomicAdd(&g_cnt[cur], cnt);
        }
        __syncthreads();   // sH read done before next convert overwrites
        buf ^= 1;
    }
}

// ---------------------------------------------------------------------------
// fused small path (1024 threads): u = mean@phiW2+b2 (zero-empty);
// v = relu(u@rhoW1+rb1); out = v@rhoW2+rb2.
// ---------------------------------------------------------------------------
__global__ __launch_bounds__(NT, 1) void rho_fused_kernel(
    const __nv_bfloat16* __restrict__ W2hi, const __nv_bfloat16* __restrict__ W2lo,
    const __nv_bfloat16* __restrict__ R1hi, const __nv_bfloat16* __restrict__ R1lo,
    const __nv_bfloat16* __restrict__ R2hi, const __nv_bfloat16* __restrict__ R2lo,
    const float* __restrict__ b2, const float* __restrict__ rb1,
    const float* __restrict__ rb2, float* __restrict__ outp, int nrows)
{
    extern __shared__ __align__(16) char smem[];
    const uint32_t sbase = smem_u32(smem);
    const int tid = threadIdx.x;
    const int wid = tid >> 5, lane = tid & 31;
    const int wm = wid & 7, wn = wid >> 3;
    const int row0 = blockIdx.x * TILE;

    float* sB = (float*)(smem + RBIAS);
    float* sCnt = (float*)(smem + RCNT);
    if (tid < D) {
        sB[tid] = b2[tid];
        sB[128 + tid] = rb1[tid];
        sB[256 + tid] = rb2[tid];
    }
    if (tid < TILE) {
        int gr = row0 + tid;
        sCnt[tid] = (gr < nrows) ? g_cnt[gr] : 0.f;
    }
    load_W_pair(smem, W2hi, W2lo, tid);
    __syncthreads();

    // A tile: mean = segsum / max(cnt,1), split hi/lo
    for (int idx = tid; idx < TILE * 32; idx += NT) {
        int r = idx >> 5, c4 = idx & 31;
        float4 v = make_float4(0.f, 0.f, 0.f, 0.f);
        int gr = row0 + r;
        if (gr < nrows) {
            v = *(const float4*)(g_segsum + (size_t)gr * D + c4 * 4);
            float s = 1.f / fmaxf(sCnt[r], 1.f);
            v.x *= s; v.y *= s; v.z *= s; v.w *= s;
        }
        float hx = __bfloat162float(__float2bfloat16_rn(v.x));
        float hy = __bfloat162float(__float2bfloat16_rn(v.y));
        float hz = __bfloat162float(__float2bfloat16_rn(v.z));
        float hw = __bfloat162float(__float2bfloat16_rn(v.w));
        uint32_t off = (uint32_t)r * SROW + (uint32_t)c4 * 8;
        *(uint2*)(smem + SA_HI + off) = make_uint2(pack_bf2(hx, hy), pack_bf2(hz, hw));
        *(uint2*)(smem + SA_LO + off) =
            make_uint2(pack_bf2(v.x - hx, v.y - hy), pack_bf2(v.z - hz, v.w - hw));
    }
    __syncthreads();

    float acc[4][4];
    // ---- stage 1: u = mean@phiW2 + b2 (zero empty rows) ----
#pragma unroll
    for (int i = 0; i < 4; i++)
#pragma unroll
        for (int j = 0; j < 4; j++) acc[i][j] = 0.f;
    gemm_pass3(sbase, acc, wm, wn, lane);
    __syncthreads();
    frag_store_A(smem, acc, sB, sCnt, false, true, wm, wn, lane);
    load_W_pair(smem, R1hi, R1lo, tid);
    __syncthreads();

    // ---- stage 2: v = relu(u@rhoW1 + rb1) ----
#pragma unroll
    for (int i = 0; i < 4; i++)
#pragma unroll
        for (int j = 0; j < 4; j++) acc[i][j] = 0.f;
    gemm_pass3(sbase, acc, wm, wn, lane);
    __syncthreads();
    frag_store_A(smem, acc, sB + 128, sCnt, true, false, wm, wn, lane);
    load_W_pair(smem, R2hi, R2lo, tid);
    __syncthreads();

    // ---- stage 3: out = v@rhoW2 + rb2 ----
#pragma unroll
    for (int i = 0; i < 4; i++)
#pragma unroll
        for (int j = 0; j < 4; j++) acc[i][j] = 0.f;
    gemm_pass3(sbase, acc, wm, wn, lane);
    {
        const int grp = lane >> 2, qp = lane & 3;
        const int rA = wm * 16 + grp;
        int gr0 = row0 + rA, gr1 = row0 + rA + 8;
#pragma unroll
        for (int nt = 0; nt < 4; nt++) {
            int c = wn * 32 + nt * 8 + qp * 2;
            float b0 = sB[256 + c], b1 = sB[256 + c + 1];
            if (gr0 < nrows)
                *(float2*)(outp + (size_t)gr0 * D + c) =
                    make_float2(acc[nt][0] + b0, acc[nt][1] + b1);
            if (gr1 < nrows)
                *(float2*)(outp + (size_t)gr1 * D + c) =
                    make_float2(acc[nt][2] + b0, acc[nt][3] + b1);
        }
    }
}

// ---------------------------------------------------------------------------
extern "C" void kernel_launch(void* const* d_in, const int* in_sizes, int n_in,
                              void* d_out, int out_size)
{
    const float* ins    = (const float*)d_in[0];
    const int*   batch  = (const int*)d_in[1];
    const float* phi_W1 = (const float*)d_in[3];
    const float* phi_b1 = (const float*)d_in[4];
    const float* phi_W2 = (const float*)d_in[5];
    const float* phi_b2 = (const float*)d_in[6];
    const float* rho_W1 = (const float*)d_in[7];
    const float* rho_b1 = (const float*)d_in[8];
    const float* rho_W2 = (const float*)d_in[9];
    const float* rho_b2 = (const float*)d_in[10];
    float* out = (float*)d_out;

    const int N = in_sizes[0] / D;
    const int ntiles = (N + TILE - 1) / TILE;

    cudaFuncSetAttribute(phi_seg_kernel, cudaFuncAttributeMaxDynamicSharedMemorySize, PHI_SMEM);
    cudaFuncSetAttribute(rho_fused_kernel, cudaFuncAttributeMaxDynamicSharedMemorySize, RHO_SMEM);

    void *p_whi = nullptr, *p_wlo = nullptr;
    cudaGetSymbolAddress(&p_whi, g_Whi);
    cudaGetSymbolAddress(&p_wlo, g_Wlo);
    const __nv_bfloat16* Whi = (const __nv_bfloat16*)p_whi;
    const __nv_bfloat16* Wlo = (const __nv_bfloat16*)p_wlo;

    int zgrid = (NSEG * D + 255) / 256;
    zero_kernel<<<zgrid, 256>>>();
    prep_kernel<<<(4 * D * D + 255) / 256, 256>>>(phi_W1, phi_W2, rho_W1, rho_W2);

    int gphi = 148;
    if (gphi > ntiles) gphi = ntiles;
    phi_seg_kernel<<<gphi, NT, PHI_SMEM>>>(ins, batch,
        Whi + 0 * D * D, Wlo + 0 * D * D, phi_b1, N, ntiles);

    int g2 = (NSEG + TILE - 1) / TILE;
    rho_fused_kernel<<<g2, NT, RHO_SMEM>>>(
        Whi + 1 * D * D, Wlo + 1 * D * D,
        Whi + 2 * D * D, Wlo + 2 * D * D,
        Whi + 3 * D * D, Wlo + 3 * D * D,
        phi_b2, rho_b1, rho_b2, out, NSEG);
}